// round 2
// baseline (speedup 1.0000x reference)
#include <cuda_runtime.h>
#include <math.h>

#define BATCH 8
#define SEQ 1900
#define EMB 256
#define NHEAD 8
#define HDIM 32
#define NTOK (BATCH*SEQ)        // 15200
#define F3 (3*EMB)              // 768
#define PADSZ 1000
#define GROUPSZ 200             // 2*single_pad
#define LNEPS 1e-5f

// ---------------- scratch (device globals, no allocations) ----------------
__device__ __align__(16) float g_q[BATCH*NHEAD*SEQ*HDIM];
__device__ __align__(16) float g_k[BATCH*NHEAD*SEQ*HDIM];
__device__ __align__(16) float g_v[BATCH*NHEAD*SEQ*HDIM];
__device__ __align__(16) float g_ctx[NTOK*EMB];
__device__ __align__(16) float g_y[NTOK*EMB];

__device__ __forceinline__ float fast_exp2(float x) {
    float y;
    asm("ex2.approx.ftz.f32 %0, %1;" : "=f"(y) : "f"(x));
    return y;
}

// ---------------------------------------------------------------------------
// Kernel 1: QKV = x @ W^T + b, scattered into q/k/v in [B,H,L,D] layout.
// Tiled 64x64, BK=32, 256 threads, 4x4 micro-tile per thread.
// ---------------------------------------------------------------------------
__global__ __launch_bounds__(256) void qkv_gemm_kernel(
    const float* __restrict__ x,      // [NTOK, 256]
    const float* __restrict__ W,      // [768, 256]
    const float* __restrict__ bias)   // [768]
{
    __shared__ __align__(16) float As[32][68];   // [k][row]
    __shared__ __align__(16) float Bs[32][68];   // [k][col(f)]

    const int n0 = blockIdx.x * 64;
    const int f0 = blockIdx.y * 64;
    const int tid = threadIdx.x;
    const int tx = tid & 15;
    const int ty = tid >> 4;

    float acc[4][4];
#pragma unroll
    for (int i = 0; i < 4; i++)
#pragma unroll
        for (int j = 0; j < 4; j++) acc[i][j] = 0.f;

    for (int k0 = 0; k0 < 256; k0 += 32) {
        // load A tile (64 rows x 32 k) transposed into As[k][row]
#pragma unroll
        for (int it = 0; it < 2; it++) {
            int idx = tid + it * 256;        // 0..511
            int row = idx >> 3;
            int kc  = (idx & 7) * 4;
            int gn = n0 + row;
            float4 val = make_float4(0.f, 0.f, 0.f, 0.f);
            if (gn < NTOK) val = *(const float4*)&x[gn * 256 + k0 + kc];
            As[kc + 0][row] = val.x;
            As[kc + 1][row] = val.y;
            As[kc + 2][row] = val.z;
            As[kc + 3][row] = val.w;
        }
        // load B tile (64 f-rows x 32 k) transposed into Bs[k][f]
#pragma unroll
        for (int it = 0; it < 2; it++) {
            int idx = tid + it * 256;
            int row = idx >> 3;
            int kc  = (idx & 7) * 4;
            int gf = f0 + row;               // < 768 always
            float4 val = *(const float4*)&W[gf * 256 + k0 + kc];
            Bs[kc + 0][row] = val.x;
            Bs[kc + 1][row] = val.y;
            Bs[kc + 2][row] = val.z;
            Bs[kc + 3][row] = val.w;
        }
        __syncthreads();

#pragma unroll
        for (int k = 0; k < 32; k++) {
            float4 a = *(const float4*)&As[k][ty * 4];
            float4 b = *(const float4*)&Bs[k][tx * 4];
            acc[0][0] += a.x * b.x; acc[0][1] += a.x * b.y; acc[0][2] += a.x * b.z; acc[0][3] += a.x * b.w;
            acc[1][0] += a.y * b.x; acc[1][1] += a.y * b.y; acc[1][2] += a.y * b.z; acc[1][3] += a.y * b.w;
            acc[2][0] += a.z * b.x; acc[2][1] += a.z * b.y; acc[2][2] += a.z * b.z; acc[2][3] += a.z * b.w;
            acc[3][0] += a.w * b.x; acc[3][1] += a.w * b.y; acc[3][2] += a.w * b.z; acc[3][3] += a.w * b.w;
        }
        __syncthreads();
    }

    // epilogue: bias + scatter to q/k/v [B,H,L,D]
#pragma unroll
    for (int i = 0; i < 4; i++) {
        int n = n0 + ty * 4 + i;
        if (n >= NTOK) continue;
        int b = n / SEQ;
        int l = n % SEQ;
#pragma unroll
        for (int j = 0; j < 4; j++) {
            int f = f0 + tx * 4 + j;
            float val = acc[i][j] + bias[f];
            int which = f >> 8;          // 0=q 1=k 2=v
            int e = f & 255;
            int h = e >> 5;
            int d = e & 31;
            float* dst = (which == 0) ? g_q : ((which == 1) ? g_k : g_v);
            dst[(((b * NHEAD) + h) * SEQ + l) * HDIM + d] = val;
        }
    }
}

// ---------------------------------------------------------------------------
// Kernel 2: flash-style masked attention. 1 thread = 1 query row.
// BM=128 rows/block, KV tile BN=32. Online softmax in exp2 domain.
// DN mask computed analytically; fully-masked KV tiles skipped.
// ---------------------------------------------------------------------------
#define BM 128
#define BN 32

__global__ __launch_bounds__(BM) void attn_kernel()
{
    const int bh = blockIdx.y;                       // b*H + h
    const int l0 = blockIdx.x * BM;
    const int l  = l0 + threadIdx.x;
    const bool active = (l < SEQ);
    const int lr = active ? l : 0;

    const float* __restrict__ qb = g_q + (size_t)bh * SEQ * HDIM;
    const float* __restrict__ kb = g_k + (size_t)bh * SEQ * HDIM;
    const float* __restrict__ vb = g_v + (size_t)bh * SEQ * HDIM;

    __shared__ __align__(16) float Ks[BN][HDIM];
    __shared__ __align__(16) float Vs[BN][HDIM];

    // q prescaled by (1/sqrt(D)) * log2(e) so scores live in exp2 domain
    const float qscale = 0.17677669529663687f * 1.4426950408889634f;

    float q[HDIM], o[HDIM];
#pragma unroll
    for (int d = 0; d < HDIM; d += 4) {
        float4 t = *(const float4*)&qb[lr * HDIM + d];
        q[d + 0] = t.x * qscale; q[d + 1] = t.y * qscale;
        q[d + 2] = t.z * qscale; q[d + 3] = t.w * qscale;
        o[d + 0] = 0.f; o[d + 1] = 0.f; o[d + 2] = 0.f; o[d + 3] = 0.f;
    }

    float mrow = -INFINITY;
    float lsum = 0.f;
    const bool row_in = (l < PADSZ);
    const int  rgroup = l / GROUPSZ;

    for (int m0 = 0; m0 < SEQ; m0 += BN) {
        // cooperative K/V tile load (zero-fill past SEQ)
#pragma unroll
        for (int it = 0; it < 2; it++) {
            int idx = threadIdx.x + it * BM;   // 0..255
            int r = idx >> 3;                  // 0..31
            int c = (idx & 7) * 4;
            int m = m0 + r;
            float4 kv = make_float4(0.f, 0.f, 0.f, 0.f);
            float4 vv = make_float4(0.f, 0.f, 0.f, 0.f);
            if (m < SEQ) {
                kv = *(const float4*)&kb[m * HDIM + c];
                vv = *(const float4*)&vb[m * HDIM + c];
            }
            *(float4*)&Ks[r][c] = kv;
            *(float4*)&Vs[r][c] = vv;
        }
        __syncthreads();

        // tile-level skip: all columns masked for this row?
        bool skip = true;
        {
            int mend = m0 + BN;
            if (mend <= PADSZ) {
                if (row_in) {
                    int gfirst = m0 / GROUPSZ;
                    int glast  = (mend - 1) / GROUPSZ;
                    skip = (rgroup < gfirst) || (rgroup > glast);
                } // else: row not in pad -> every col in pad masked -> skip
            } else {
                skip = false;
            }
        }

        if (active && !skip) {
            float s[BN];
#pragma unroll
            for (int j = 0; j < BN; j++) {
                float a = 0.f;
#pragma unroll
                for (int d = 0; d < HDIM; d += 4) {
                    float4 kk = *(const float4*)&Ks[j][d];
                    a += q[d] * kk.x + q[d + 1] * kk.y + q[d + 2] * kk.z + q[d + 3] * kk.w;
                }
                int m = m0 + j;
                bool masked = (m >= SEQ) ||
                              ((m < PADSZ) && (!row_in || (rgroup != m / GROUPSZ)));
                s[j] = masked ? -INFINITY : a;
            }

            float tmax = -INFINITY;
#pragma unroll
            for (int j = 0; j < BN; j++) tmax = fmaxf(tmax, s[j]);

            float m_new = fmaxf(mrow, tmax);
            if (m_new != -INFINITY) {
                if (m_new > mrow) {
                    float corr = fast_exp2(mrow - m_new);   // 0 if mrow==-inf
                    lsum *= corr;
#pragma unroll
                    for (int d = 0; d < HDIM; d++) o[d] *= corr;
                    mrow = m_new;
                }
#pragma unroll
                for (int j = 0; j < BN; j++) {
                    float p = fast_exp2(s[j] - mrow);       // 0 for masked
                    lsum += p;
#pragma unroll
                    for (int d = 0; d < HDIM; d += 4) {
                        float4 vv = *(const float4*)&Vs[j][d];
                        o[d + 0] += p * vv.x; o[d + 1] += p * vv.y;
                        o[d + 2] += p * vv.z; o[d + 3] += p * vv.w;
                    }
                }
            }
        }
        __syncthreads();
    }

    if (active) {
        float inv = 1.0f / lsum;   // every row has unmasked cols (m >= PADSZ)
        int b = bh >> 3;
        int h = bh & 7;
        float* dst = &g_ctx[((size_t)b * SEQ + l) * EMB + h * HDIM];
#pragma unroll
        for (int d = 0; d < HDIM; d += 4) {
            float4 w;
            w.x = o[d + 0] * inv; w.y = o[d + 1] * inv;
            w.z = o[d + 2] * inv; w.w = o[d + 3] * inv;
            *(float4*)&dst[d] = w;
        }
    }
}

// ---------------------------------------------------------------------------
// Kernel 3: y = x + ctx @ out_w^T + out_b   (tiled 64x64 like kernel 1)
// ---------------------------------------------------------------------------
__global__ __launch_bounds__(256) void out_gemm_kernel(
    const float* __restrict__ x,      // [NTOK, 256]
    const float* __restrict__ W,      // [256, 256]
    const float* __restrict__ bias)   // [256]
{
    __shared__ __align__(16) float As[32][68];
    __shared__ __align__(16) float Bs[32][68];

    const int n0 = blockIdx.x * 64;
    const int f0 = blockIdx.y * 64;
    const int tid = threadIdx.x;
    const int tx = tid & 15;
    const int ty = tid >> 4;

    float acc[4][4];
#pragma unroll
    for (int i = 0; i < 4; i++)
#pragma unroll
        for (int j = 0; j < 4; j++) acc[i][j] = 0.f;

    for (int k0 = 0; k0 < 256; k0 += 32) {
#pragma unroll
        for (int it = 0; it < 2; it++) {
            int idx = tid + it * 256;
            int row = idx >> 3;
            int kc  = (idx & 7) * 4;
            int gn = n0 + row;
            float4 val = make_float4(0.f, 0.f, 0.f, 0.f);
            if (gn < NTOK) val = *(const float4*)&g_ctx[gn * 256 + k0 + kc];
            As[kc + 0][row] = val.x;
            As[kc + 1][row] = val.y;
            As[kc + 2][row] = val.z;
            As[kc + 3][row] = val.w;
        }
#pragma unroll
        for (int it = 0; it < 2; it++) {
            int idx = tid + it * 256;
            int row = idx >> 3;
            int kc  = (idx & 7) * 4;
            int gf = f0 + row;               // < 256
            float4 val = *(const float4*)&W[gf * 256 + k0 + kc];
            Bs[kc + 0][row] = val.x;
            Bs[kc + 1][row] = val.y;
            Bs[kc + 2][row] = val.z;
            Bs[kc + 3][row] = val.w;
        }
        __syncthreads();

#pragma unroll
        for (int k = 0; k < 32; k++) {
            float4 a = *(const float4*)&As[k][ty * 4];
            float4 b = *(const float4*)&Bs[k][tx * 4];
            acc[0][0] += a.x * b.x; acc[0][1] += a.x * b.y; acc[0][2] += a.x * b.z; acc[0][3] += a.x * b.w;
            acc[1][0] += a.y * b.x; acc[1][1] += a.y * b.y; acc[1][2] += a.y * b.z; acc[1][3] += a.y * b.w;
            acc[2][0] += a.z * b.x; acc[2][1] += a.z * b.y; acc[2][2] += a.z * b.z; acc[2][3] += a.z * b.w;
            acc[3][0] += a.w * b.x; acc[3][1] += a.w * b.y; acc[3][2] += a.w * b.z; acc[3][3] += a.w * b.w;
        }
        __syncthreads();
    }

#pragma unroll
    for (int i = 0; i < 4; i++) {
        int n = n0 + ty * 4 + i;
        if (n >= NTOK) continue;
#pragma unroll
        for (int j = 0; j < 4; j++) {
            int f = f0 + tx * 4 + j;
            g_y[n * 256 + f] = acc[i][j] + bias[f] + x[n * 256 + f];
        }
    }
}

// ---------------------------------------------------------------------------
// Kernel 4: row LayerNorm, one block per token
// ---------------------------------------------------------------------------
__global__ __launch_bounds__(256) void ln_kernel(
    const float* __restrict__ gamma,
    const float* __restrict__ beta,
    float* __restrict__ out)
{
    const int n = blockIdx.x;
    const int f = threadIdx.x;
    float v = g_y[n * 256 + f];

    float s1 = v, s2 = v * v;
#pragma unroll
    for (int off = 16; off > 0; off >>= 1) {
        s1 += __shfl_xor_sync(0xffffffffu, s1, off);
        s2 += __shfl_xor_sync(0xffffffffu, s2, off);
    }
    __shared__ float a1[8], a2[8];
    int w = f >> 5, ln = f & 31;
    if (ln == 0) { a1[w] = s1; a2[w] = s2; }
    __syncthreads();
    float S1 = 0.f, S2 = 0.f;
#pragma unroll
    for (int i = 0; i < 8; i++) { S1 += a1[i]; S2 += a2[i]; }

    float mean = S1 * (1.0f / 256.0f);
    float var  = S2 * (1.0f / 256.0f) - mean * mean;
    float r = rsqrtf(var + LNEPS);
    out[n * 256 + f] = (v - mean) * r * gamma[f] + beta[f];
}

// ---------------------------------------------------------------------------
extern "C" void kernel_launch(void* const* d_in, const int* in_sizes, int n_in,
                              void* d_out, int out_size)
{
    const float* x     = (const float*)d_in[0];
    const float* in_w  = (const float*)d_in[1];
    const float* in_b  = (const float*)d_in[2];
    const float* out_w = (const float*)d_in[3];
    const float* out_b = (const float*)d_in[4];
    const float* ln_g  = (const float*)d_in[5];
    const float* ln_b  = (const float*)d_in[6];
    float* out = (float*)d_out;

    qkv_gemm_kernel<<<dim3((NTOK + 63) / 64, F3 / 64), 256>>>(x, in_w, in_b);
    attn_kernel<<<dim3((SEQ + BM - 1) / BM, BATCH * NHEAD), BM>>>();
    out_gemm_kernel<<<dim3((NTOK + 63) / 64, EMB / 64), 256>>>(x, out_w, out_b);
    ln_kernel<<<NTOK, 256>>>(ln_g, ln_b, out);
}

// round 4
// speedup vs baseline: 2.1674x; 2.1674x over previous
#include <cuda_runtime.h>
#include <math.h>
#include <stdint.h>

#define BATCH 8
#define SEQ 1900
#define EMB 256
#define NHEAD 8
#define HDIM 32
#define NTOK (BATCH*SEQ)        // 15200
#define F3 (3*EMB)              // 768
#define PADSZ 1000
#define GROUPSZ 200             // 2*single_pad
#define LNEPS 1e-5f

// ---------------- scratch (device globals, no allocations) ----------------
__device__ __align__(16) float g_q[BATCH*NHEAD*SEQ*HDIM];
__device__ __align__(16) float g_k[BATCH*NHEAD*SEQ*HDIM];
__device__ __align__(16) float g_v[BATCH*NHEAD*SEQ*HDIM];
__device__ __align__(16) float g_ctx[NTOK*EMB];
__device__ __align__(16) float g_y[NTOK*EMB];

__device__ __forceinline__ float fast_exp2(float x) {
    float y;
    asm("ex2.approx.ftz.f32 %0, %1;" : "=f"(y) : "f"(x));
    return y;
}

__device__ __forceinline__ uint32_t f2tf32(float f) {
    uint32_t u;
    asm("cvt.rna.tf32.f32 %0, %1;" : "=r"(u) : "f"(f));
    return u;
}

__device__ __forceinline__ void mma_tf32(float& c0, float& c1, float& c2, float& c3,
                                         uint32_t a0, uint32_t a1, uint32_t a2, uint32_t a3,
                                         uint32_t b0, uint32_t b1) {
    asm volatile(
        "mma.sync.aligned.m16n8k8.row.col.f32.tf32.tf32.f32 "
        "{%0,%1,%2,%3}, {%4,%5,%6,%7}, {%8,%9}, {%0,%1,%2,%3};"
        : "+f"(c0), "+f"(c1), "+f"(c2), "+f"(c3)
        : "r"(a0), "r"(a1), "r"(a2), "r"(a3), "r"(b0), "r"(b1));
}

// ---------------------------------------------------------------------------
// Kernel 1: QKV = x @ W^T + b, scattered into q/k/v in [B,H,L,D] layout.
// ---------------------------------------------------------------------------
__global__ __launch_bounds__(256) void qkv_gemm_kernel(
    const float* __restrict__ x,      // [NTOK, 256]
    const float* __restrict__ W,      // [768, 256]
    const float* __restrict__ bias)   // [768]
{
    __shared__ __align__(16) float As[32][68];   // [k][row]
    __shared__ __align__(16) float Bs[32][68];   // [k][col(f)]

    const int n0 = blockIdx.x * 64;
    const int f0 = blockIdx.y * 64;
    const int tid = threadIdx.x;
    const int tx = tid & 15;
    const int ty = tid >> 4;

    float acc[4][4];
#pragma unroll
    for (int i = 0; i < 4; i++)
#pragma unroll
        for (int j = 0; j < 4; j++) acc[i][j] = 0.f;

    for (int k0 = 0; k0 < 256; k0 += 32) {
#pragma unroll
        for (int it = 0; it < 2; it++) {
            int idx = tid + it * 256;
            int row = idx >> 3;
            int kc  = (idx & 7) * 4;
            int gn = n0 + row;
            float4 val = make_float4(0.f, 0.f, 0.f, 0.f);
            if (gn < NTOK) val = *(const float4*)&x[gn * 256 + k0 + kc];
            As[kc + 0][row] = val.x;
            As[kc + 1][row] = val.y;
            As[kc + 2][row] = val.z;
            As[kc + 3][row] = val.w;
        }
#pragma unroll
        for (int it = 0; it < 2; it++) {
            int idx = tid + it * 256;
            int row = idx >> 3;
            int kc  = (idx & 7) * 4;
            int gf = f0 + row;
            float4 val = *(const float4*)&W[gf * 256 + k0 + kc];
            Bs[kc + 0][row] = val.x;
            Bs[kc + 1][row] = val.y;
            Bs[kc + 2][row] = val.z;
            Bs[kc + 3][row] = val.w;
        }
        __syncthreads();

#pragma unroll
        for (int k = 0; k < 32; k++) {
            float4 a = *(const float4*)&As[k][ty * 4];
            float4 b = *(const float4*)&Bs[k][tx * 4];
            acc[0][0] += a.x * b.x; acc[0][1] += a.x * b.y; acc[0][2] += a.x * b.z; acc[0][3] += a.x * b.w;
            acc[1][0] += a.y * b.x; acc[1][1] += a.y * b.y; acc[1][2] += a.y * b.z; acc[1][3] += a.y * b.w;
            acc[2][0] += a.z * b.x; acc[2][1] += a.z * b.y; acc[2][2] += a.z * b.z; acc[2][3] += a.z * b.w;
            acc[3][0] += a.w * b.x; acc[3][1] += a.w * b.y; acc[3][2] += a.w * b.z; acc[3][3] += a.w * b.w;
        }
        __syncthreads();
    }

#pragma unroll
    for (int i = 0; i < 4; i++) {
        int n = n0 + ty * 4 + i;
        if (n >= NTOK) continue;
        int b = n / SEQ;
        int l = n % SEQ;
#pragma unroll
        for (int j = 0; j < 4; j++) {
            int f = f0 + tx * 4 + j;
            float val = acc[i][j] + bias[f];
            int which = f >> 8;
            int e = f & 255;
            int h = e >> 5;
            int d = e & 31;
            float* dst = (which == 0) ? g_q : ((which == 1) ? g_k : g_v);
            dst[(((b * NHEAD) + h) * SEQ + l) * HDIM + d] = val;
        }
    }
}

// ---------------------------------------------------------------------------
// Kernel 2: flash attention with tf32 warp MMA.
// Block = 128 threads (4 warps), 64 query rows (16/warp). KV tiles of 64.
// K/V staged in smem as tf32 with XOR swizzle; online softmax in exp2 domain.
// ---------------------------------------------------------------------------
__global__ __launch_bounds__(128) void attn_mma_kernel()
{
    const int bh  = blockIdx.y;                 // b*H + h
    const int l0  = blockIdx.x * 64;
    const int wid = threadIdx.x >> 5;
    const int lane = threadIdx.x & 31;
    const int g = lane >> 2;                    // 0..7
    const int t = lane & 3;                     // 0..3
    const int r_lo = l0 + wid * 16 + g;
    const int r_hi = r_lo + 8;

    const float* __restrict__ qb = g_q + (size_t)bh * SEQ * HDIM;
    const float* __restrict__ kb = g_k + (size_t)bh * SEQ * HDIM;
    const float* __restrict__ vb = g_v + (size_t)bh * SEQ * HDIM;

    // smem: tf32 bits, layout [row][col] with col XOR-swizzled by (row&7)*4
    __shared__ uint32_t Ks[64 * 32];
    __shared__ uint32_t Vs[64 * 32];

    // Q as tf32 A-fragments, prescaled by 1/sqrt(D) * log2(e)
    const float qscale = 0.17677669529663687f * 1.4426950408889634f;
    uint32_t Aq[4][4];
#pragma unroll
    for (int s = 0; s < 4; s++) {
        float q00 = 0.f, q10 = 0.f, q01 = 0.f, q11 = 0.f;
        if (r_lo < SEQ) {
            q00 = qb[r_lo * HDIM + 8 * s + t];
            q01 = qb[r_lo * HDIM + 8 * s + t + 4];
        }
        if (r_hi < SEQ) {
            q10 = qb[r_hi * HDIM + 8 * s + t];
            q11 = qb[r_hi * HDIM + 8 * s + t + 4];
        }
        Aq[s][0] = f2tf32(q00 * qscale);
        Aq[s][1] = f2tf32(q10 * qscale);
        Aq[s][2] = f2tf32(q01 * qscale);
        Aq[s][3] = f2tf32(q11 * qscale);
    }

    float o[4][4];
#pragma unroll
    for (int nn = 0; nn < 4; nn++)
#pragma unroll
        for (int e = 0; e < 4; e++) o[nn][e] = 0.f;

    float m_lo = -INFINITY, m_hi = -INFINITY;
    float l_lo = 0.f, l_hi = 0.f;

    const int glo = (r_lo < PADSZ) ? (r_lo / GROUPSZ) : -1;
    const int ghi = (r_hi < PADSZ) ? (r_hi / GROUPSZ) : -1;
    const bool blk_has_pad = (l0 < PADSZ);
    const int gminb = l0 / GROUPSZ;
    const int gmaxb = (min(l0 + 63, PADSZ - 1)) / GROUPSZ;

    for (int m0 = 0; m0 < SEQ; m0 += 64) {
        // block-uniform tile skip
        bool needed = (m0 + 64 > PADSZ);
        if (!needed) {
            if (blk_has_pad) {
                int gt0 = m0 / GROUPSZ, gt1 = (m0 + 63) / GROUPSZ;
                needed = !(gmaxb < gt0 || gminb > gt1);
            }
        }
        if (!needed) continue;

        __syncthreads();
        // cooperative K/V tile load: 64 rows x 32 cols, tf32 + swizzle
#pragma unroll
        for (int it = 0; it < 4; it++) {
            int chunk = threadIdx.x + it * 128;     // 0..511
            int row = chunk >> 3;
            int c4  = (chunk & 7) * 4;
            int m = m0 + row;
            float4 kv = make_float4(0.f, 0.f, 0.f, 0.f);
            float4 vv = make_float4(0.f, 0.f, 0.f, 0.f);
            if (m < SEQ) {
                kv = *(const float4*)&kb[m * HDIM + c4];
                vv = *(const float4*)&vb[m * HDIM + c4];
            }
            int off = row * 32 + (c4 ^ ((row & 7) << 2));
            Ks[off + 0] = f2tf32(kv.x); Ks[off + 1] = f2tf32(kv.y);
            Ks[off + 2] = f2tf32(kv.z); Ks[off + 3] = f2tf32(kv.w);
            Vs[off + 0] = f2tf32(vv.x); Vs[off + 1] = f2tf32(vv.y);
            Vs[off + 2] = f2tf32(vv.z); Vs[off + 3] = f2tf32(vv.w);
        }
        __syncthreads();

        // --- scores: S = Q @ K^T (16x64 per warp) ---
        float S[8][4];
#pragma unroll
        for (int j = 0; j < 8; j++) {
            S[j][0] = 0.f; S[j][1] = 0.f; S[j][2] = 0.f; S[j][3] = 0.f;
            int nrow = 8 * j + g;
            int base = nrow * 32;
            int swz = g << 2;
#pragma unroll
            for (int s = 0; s < 4; s++) {
                uint32_t b0 = Ks[base + ((8 * s + t) ^ swz)];
                uint32_t b1 = Ks[base + ((8 * s + t + 4) ^ swz)];
                mma_tf32(S[j][0], S[j][1], S[j][2], S[j][3],
                         Aq[s][0], Aq[s][1], Aq[s][2], Aq[s][3], b0, b1);
            }
        }

        // --- mask + row max ---
        float tmax_lo = -INFINITY, tmax_hi = -INFINITY;
#pragma unroll
        for (int j = 0; j < 8; j++) {
            int c0 = m0 + 8 * j + 2 * t;
            int c1 = c0 + 1;
            int mg0 = c0 / GROUPSZ;
            int mg1 = c1 / GROUPSZ;
            bool b0lo = (c0 >= SEQ) || (c0 < PADSZ && mg0 != glo);
            bool b1lo = (c1 >= SEQ) || (c1 < PADSZ && mg1 != glo);
            bool b0hi = (c0 >= SEQ) || (c0 < PADSZ && mg0 != ghi);
            bool b1hi = (c1 >= SEQ) || (c1 < PADSZ && mg1 != ghi);
            if (b0lo) S[j][0] = -INFINITY;
            if (b1lo) S[j][1] = -INFINITY;
            if (b0hi) S[j][2] = -INFINITY;
            if (b1hi) S[j][3] = -INFINITY;
            tmax_lo = fmaxf(tmax_lo, fmaxf(S[j][0], S[j][1]));
            tmax_hi = fmaxf(tmax_hi, fmaxf(S[j][2], S[j][3]));
        }
        // quad reduce (lanes sharing a row)
        tmax_lo = fmaxf(tmax_lo, __shfl_xor_sync(0xffffffffu, tmax_lo, 1));
        tmax_lo = fmaxf(tmax_lo, __shfl_xor_sync(0xffffffffu, tmax_lo, 2));
        tmax_hi = fmaxf(tmax_hi, __shfl_xor_sync(0xffffffffu, tmax_hi, 1));
        tmax_hi = fmaxf(tmax_hi, __shfl_xor_sync(0xffffffffu, tmax_hi, 2));

        float mnew_lo = fmaxf(m_lo, tmax_lo);
        float mnew_hi = fmaxf(m_hi, tmax_hi);
        float msafe_lo = (mnew_lo == -INFINITY) ? 0.f : mnew_lo;
        float msafe_hi = (mnew_hi == -INFINITY) ? 0.f : mnew_hi;
        float corr_lo = fast_exp2(m_lo - msafe_lo);   // 0 if m_lo == -inf
        float corr_hi = fast_exp2(m_hi - msafe_hi);
        m_lo = mnew_lo; m_hi = mnew_hi;

        l_lo *= corr_lo;
        l_hi *= corr_hi;
#pragma unroll
        for (int nn = 0; nn < 4; nn++) {
            o[nn][0] *= corr_lo; o[nn][1] *= corr_lo;
            o[nn][2] *= corr_hi; o[nn][3] *= corr_hi;
        }

        // --- p = exp2(S - m), accumulate row sums (per-lane partials) ---
#pragma unroll
        for (int j = 0; j < 8; j++) {
            S[j][0] = fast_exp2(S[j][0] - msafe_lo);
            S[j][1] = fast_exp2(S[j][1] - msafe_lo);
            S[j][2] = fast_exp2(S[j][2] - msafe_hi);
            S[j][3] = fast_exp2(S[j][3] - msafe_hi);
            l_lo += S[j][0] + S[j][1];
            l_hi += S[j][2] + S[j][3];
        }

        // --- PV: o += P(16x64) @ V(64x32) ---
#pragma unroll
        for (int c = 0; c < 8; c++) {
            // convert C-layout frag c (cols 8c..8c+7) into A-layout for k-chunk c
            int src0 = (lane & ~3) | (t >> 1);
            int src1 = (lane & ~3) | (2 + (t >> 1));
            float x0 = __shfl_sync(0xffffffffu, S[c][0], src0);
            float x1 = __shfl_sync(0xffffffffu, S[c][1], src0);
            float y0 = __shfl_sync(0xffffffffu, S[c][0], src1);
            float y1 = __shfl_sync(0xffffffffu, S[c][1], src1);
            float z0 = __shfl_sync(0xffffffffu, S[c][2], src0);
            float z1 = __shfl_sync(0xffffffffu, S[c][3], src0);
            float w0 = __shfl_sync(0xffffffffu, S[c][2], src1);
            float w1 = __shfl_sync(0xffffffffu, S[c][3], src1);
            bool odd = (t & 1);
            uint32_t a0 = f2tf32(odd ? x1 : x0);   // (r_lo, 8c+t)
            uint32_t a1 = f2tf32(odd ? z1 : z0);   // (r_hi, 8c+t)
            uint32_t a2 = f2tf32(odd ? y1 : y0);   // (r_lo, 8c+t+4)
            uint32_t a3 = f2tf32(odd ? w1 : w0);   // (r_hi, 8c+t+4)

            int krow0 = 8 * c + t;
            int krow1 = krow0 + 4;
            int base0 = krow0 * 32;
            int base1 = krow1 * 32;
            int swz0 = t << 2;
            int swz1 = (t + 4) << 2;
#pragma unroll
            for (int nn = 0; nn < 4; nn++) {
                uint32_t b0 = Vs[base0 + ((8 * nn + g) ^ swz0)];
                uint32_t b1 = Vs[base1 + ((8 * nn + g) ^ swz1)];
                mma_tf32(o[nn][0], o[nn][1], o[nn][2], o[nn][3],
                         a0, a1, a2, a3, b0, b1);
            }
        }
    }

    // finalize: quad-reduce row sums, normalize, store
    l_lo += __shfl_xor_sync(0xffffffffu, l_lo, 1);
    l_lo += __shfl_xor_sync(0xffffffffu, l_lo, 2);
    l_hi += __shfl_xor_sync(0xffffffffu, l_hi, 1);
    l_hi += __shfl_xor_sync(0xffffffffu, l_hi, 2);
    float inv_lo = 1.0f / l_lo;
    float inv_hi = 1.0f / l_hi;

    const int b = bh >> 3;
    const int h = bh & 7;
    if (r_lo < SEQ) {
        float* dst = &g_ctx[((size_t)b * SEQ + r_lo) * EMB + h * HDIM];
#pragma unroll
        for (int nn = 0; nn < 4; nn++) {
            float2 w2 = make_float2(o[nn][0] * inv_lo, o[nn][1] * inv_lo);
            *(float2*)&dst[8 * nn + 2 * t] = w2;
        }
    }
    if (r_hi < SEQ) {
        float* dst = &g_ctx[((size_t)b * SEQ + r_hi) * EMB + h * HDIM];
#pragma unroll
        for (int nn = 0; nn < 4; nn++) {
            float2 w2 = make_float2(o[nn][2] * inv_hi, o[nn][3] * inv_hi);
            *(float2*)&dst[8 * nn + 2 * t] = w2;
        }
    }
}

// ---------------------------------------------------------------------------
// Kernel 3: y = x + ctx @ out_w^T + out_b
// ---------------------------------------------------------------------------
__global__ __launch_bounds__(256) void out_gemm_kernel(
    const float* __restrict__ x,
    const float* __restrict__ W,
    const float* __restrict__ bias)
{
    __shared__ __align__(16) float As[32][68];
    __shared__ __align__(16) float Bs[32][68];

    const int n0 = blockIdx.x * 64;
    const int f0 = blockIdx.y * 64;
    const int tid = threadIdx.x;
    const int tx = tid & 15;
    const int ty = tid >> 4;

    float acc[4][4];
#pragma unroll
    for (int i = 0; i < 4; i++)
#pragma unroll
        for (int j = 0; j < 4; j++) acc[i][j] = 0.f;

    for (int k0 = 0; k0 < 256; k0 += 32) {
#pragma unroll
        for (int it = 0; it < 2; it++) {
            int idx = tid + it * 256;
            int row = idx >> 3;
            int kc  = (idx & 7) * 4;
            int gn = n0 + row;
            float4 val = make_float4(0.f, 0.f, 0.f, 0.f);
            if (gn < NTOK) val = *(const float4*)&g_ctx[gn * 256 + k0 + kc];
            As[kc + 0][row] = val.x;
            As[kc + 1][row] = val.y;
            As[kc + 2][row] = val.z;
            As[kc + 3][row] = val.w;
        }
#pragma unroll
        for (int it = 0; it < 2; it++) {
            int idx = tid + it * 256;
            int row = idx >> 3;
            int kc  = (idx & 7) * 4;
            int gf = f0 + row;
            float4 val = *(const float4*)&W[gf * 256 + k0 + kc];
            Bs[kc + 0][row] = val.x;
            Bs[kc + 1][row] = val.y;
            Bs[kc + 2][row] = val.z;
            Bs[kc + 3][row] = val.w;
        }
        __syncthreads();

#pragma unroll
        for (int k = 0; k < 32; k++) {
            float4 a = *(const float4*)&As[k][ty * 4];
            float4 b = *(const float4*)&Bs[k][tx * 4];
            acc[0][0] += a.x * b.x; acc[0][1] += a.x * b.y; acc[0][2] += a.x * b.z; acc[0][3] += a.x * b.w;
            acc[1][0] += a.y * b.x; acc[1][1] += a.y * b.y; acc[1][2] += a.y * b.z; acc[1][3] += a.y * b.w;
            acc[2][0] += a.z * b.x; acc[2][1] += a.z * b.y; acc[2][2] += a.z * b.z; acc[2][3] += a.z * b.w;
            acc[3][0] += a.w * b.x; acc[3][1] += a.w * b.y; acc[3][2] += a.w * b.z; acc[3][3] += a.w * b.w;
        }
        __syncthreads();
    }

#pragma unroll
    for (int i = 0; i < 4; i++) {
        int n = n0 + ty * 4 + i;
        if (n >= NTOK) continue;
#pragma unroll
        for (int j = 0; j < 4; j++) {
            int f = f0 + tx * 4 + j;
            g_y[n * 256 + f] = acc[i][j] + bias[f] + x[n * 256 + f];
        }
    }
}

// ---------------------------------------------------------------------------
// Kernel 4: row LayerNorm
// ---------------------------------------------------------------------------
__global__ __launch_bounds__(256) void ln_kernel(
    const float* __restrict__ gamma,
    const float* __restrict__ beta,
    float* __restrict__ out)
{
    const int n = blockIdx.x;
    const int f = threadIdx.x;
    float v = g_y[n * 256 + f];

    float s1 = v, s2 = v * v;
#pragma unroll
    for (int off = 16; off > 0; off >>= 1) {
        s1 += __shfl_xor_sync(0xffffffffu, s1, off);
        s2 += __shfl_xor_sync(0xffffffffu, s2, off);
    }
    __shared__ float a1[8], a2[8];
    int w = f >> 5, ln = f & 31;
    if (ln == 0) { a1[w] = s1; a2[w] = s2; }
    __syncthreads();
    float S1 = 0.f, S2 = 0.f;
#pragma unroll
    for (int i = 0; i < 8; i++) { S1 += a1[i]; S2 += a2[i]; }

    float mean = S1 * (1.0f / 256.0f);
    float var  = S2 * (1.0f / 256.0f) - mean * mean;
    float r = rsqrtf(var + LNEPS);
    out[n * 256 + f] = (v - mean) * r * gamma[f] + beta[f];
}

// ---------------------------------------------------------------------------
extern "C" void kernel_launch(void* const* d_in, const int* in_sizes, int n_in,
                              void* d_out, int out_size)
{
    const float* x     = (const float*)d_in[0];
    const float* in_w  = (const float*)d_in[1];
    const float* in_b  = (const float*)d_in[2];
    const float* out_w = (const float*)d_in[3];
    const float* out_b = (const float*)d_in[4];
    const float* ln_g  = (const float*)d_in[5];
    const float* ln_b  = (const float*)d_in[6];
    float* out = (float*)d_out;

    qkv_gemm_kernel<<<dim3((NTOK + 63) / 64, F3 / 64), 256>>>(x, in_w, in_b);
    attn_mma_kernel<<<dim3((SEQ + 63) / 64, BATCH * NHEAD), 128>>>();
    out_gemm_kernel<<<dim3((NTOK + 63) / 64, EMB / 64), 256>>>(x, out_w, out_b);
    ln_kernel<<<NTOK, 256>>>(ln_g, ln_b, out);
}

// round 5
// speedup vs baseline: 3.2099x; 1.4810x over previous
#include <cuda_runtime.h>
#include <math.h>
#include <stdint.h>

#define BATCH 8
#define SEQ 1900
#define EMB 256
#define NHEAD 8
#define HDIM 32
#define NTOK (BATCH*SEQ)        // 15200
#define F3 (3*EMB)              // 768
#define PADSZ 1000
#define GROUPSZ 200             // 2*single_pad
#define LNEPS 1e-5f

// ---------------- scratch (device globals, no allocations) ----------------
__device__ __align__(16) float g_q[BATCH*NHEAD*SEQ*HDIM];
__device__ __align__(16) float g_k[BATCH*NHEAD*SEQ*HDIM];
__device__ __align__(16) float g_v[BATCH*NHEAD*SEQ*HDIM];
__device__ __align__(16) float g_ctx[NTOK*EMB];
__device__ __align__(16) float g_y[NTOK*EMB];

__device__ __forceinline__ float fast_exp2(float x) {
    float y;
    asm("ex2.approx.ftz.f32 %0, %1;" : "=f"(y) : "f"(x));
    return y;
}

__device__ __forceinline__ uint32_t f2tf32(float f) {
    uint32_t u;
    asm("cvt.rna.tf32.f32 %0, %1;" : "=r"(u) : "f"(f));
    return u;
}

__device__ __forceinline__ void mma_tf32(float& c0, float& c1, float& c2, float& c3,
                                         uint32_t a0, uint32_t a1, uint32_t a2, uint32_t a3,
                                         uint32_t b0, uint32_t b1) {
    asm volatile(
        "mma.sync.aligned.m16n8k8.row.col.f32.tf32.tf32.f32 "
        "{%0,%1,%2,%3}, {%4,%5,%6,%7}, {%8,%9}, {%0,%1,%2,%3};"
        : "+f"(c0), "+f"(c1), "+f"(c2), "+f"(c3)
        : "r"(a0), "r"(a1), "r"(a2), "r"(a3), "r"(b0), "r"(b1));
}

// ===========================================================================
// tf32 MMA GEMM core: out[n, f] = sum_k A[n,k] * W[f,k]
// Block: 128 threads (4 warps). Tile: 64(M) x 64(N), BK=64, K=256.
// Each warp computes 16 rows x 64 cols. A/B staged in smem (fp32 bits,
// HMMA truncates to tf32), XOR swizzle -> conflict-free fragment LDS.
// ===========================================================================
struct MmaTile {
    float C[8][4];
};

__device__ __forceinline__ void gemm_mainloop(
    const float* __restrict__ A, int a_rows,     // [a_rows, 256]
    const float* __restrict__ W,                 // [*, 256]
    int n0, int f0, int tid, int wid, int g, int t,
    uint32_t* As, uint32_t* Bs, MmaTile& acc)
{
#pragma unroll
    for (int nn = 0; nn < 8; nn++) {
        acc.C[nn][0] = 0.f; acc.C[nn][1] = 0.f;
        acc.C[nn][2] = 0.f; acc.C[nn][3] = 0.f;
    }

    const int sw = g << 2;
    const int ra = (16 * wid + g) * 64;
    const int rb = ra + 8 * 64;

    for (int k0 = 0; k0 < 256; k0 += 64) {
        // stage A tile 64x64 and B tile 64x64 (fp32 bits)
#pragma unroll
        for (int it = 0; it < 8; it++) {
            int idx = tid + it * 128;         // 0..1023
            int row = idx >> 4;               // 0..63
            int c4  = (idx & 15) * 4;         // 0..60
            int off = row * 64 + (c4 ^ ((row & 7) << 2));

            int gn = n0 + row;
            float4 va = make_float4(0.f, 0.f, 0.f, 0.f);
            if (gn < a_rows) va = *(const float4*)&A[(size_t)gn * 256 + k0 + c4];
            As[off + 0] = __float_as_uint(va.x);
            As[off + 1] = __float_as_uint(va.y);
            As[off + 2] = __float_as_uint(va.z);
            As[off + 3] = __float_as_uint(va.w);

            float4 vb = *(const float4*)&W[(size_t)(f0 + row) * 256 + k0 + c4];
            Bs[off + 0] = __float_as_uint(vb.x);
            Bs[off + 1] = __float_as_uint(vb.y);
            Bs[off + 2] = __float_as_uint(vb.z);
            Bs[off + 3] = __float_as_uint(vb.w);
        }
        __syncthreads();

        // A fragments for all 8 k-subchunks
        uint32_t Af[8][4];
#pragma unroll
        for (int s = 0; s < 8; s++) {
            Af[s][0] = As[ra + ((8 * s + t) ^ sw)];
            Af[s][1] = As[rb + ((8 * s + t) ^ sw)];
            Af[s][2] = As[ra + ((8 * s + t + 4) ^ sw)];
            Af[s][3] = As[rb + ((8 * s + t + 4) ^ sw)];
        }

#pragma unroll
        for (int s = 0; s < 8; s++) {
#pragma unroll
            for (int nn = 0; nn < 8; nn++) {
                int fb = (8 * nn + g) * 64;
                uint32_t b0 = Bs[fb + ((8 * s + t) ^ sw)];
                uint32_t b1 = Bs[fb + ((8 * s + t + 4) ^ sw)];
                mma_tf32(acc.C[nn][0], acc.C[nn][1], acc.C[nn][2], acc.C[nn][3],
                         Af[s][0], Af[s][1], Af[s][2], Af[s][3], b0, b1);
            }
        }
        __syncthreads();
    }
}

// ---------------------------------------------------------------------------
// Kernel 1: QKV = x @ W^T + b, scattered into q/k/v in [B,H,L,D] layout.
// ---------------------------------------------------------------------------
__global__ __launch_bounds__(128) void qkv_mma_kernel(
    const float* __restrict__ x,      // [NTOK, 256]
    const float* __restrict__ W,      // [768, 256]
    const float* __restrict__ bias)   // [768]
{
    __shared__ uint32_t As[64 * 64];
    __shared__ uint32_t Bs[64 * 64];

    const int n0 = blockIdx.x * 64;
    const int f0 = blockIdx.y * 64;
    const int tid = threadIdx.x;
    const int wid = tid >> 5;
    const int lane = tid & 31;
    const int g = lane >> 2;
    const int t = lane & 3;

    MmaTile acc;
    gemm_mainloop(x, NTOK, W, n0, f0, tid, wid, g, t, As, Bs, acc);

    // epilogue: bias + scatter
    const int r0 = n0 + 16 * wid + g;
    const int r1 = r0 + 8;
#pragma unroll
    for (int half = 0; half < 2; half++) {
        int n = half ? r1 : r0;
        if (n >= NTOK) continue;
        int b = n / SEQ;
        int l = n % SEQ;
#pragma unroll
        for (int nn = 0; nn < 8; nn++) {
            int f = f0 + 8 * nn + 2 * t;
            float v0 = (half ? acc.C[nn][2] : acc.C[nn][0]) + bias[f];
            float v1 = (half ? acc.C[nn][3] : acc.C[nn][1]) + bias[f + 1];
            int which = f >> 8;
            int e = f & 255;
            int h = e >> 5;
            int d = e & 31;
            float* dst = (which == 0) ? g_q : ((which == 1) ? g_k : g_v);
            *(float2*)&dst[(((b * NHEAD) + h) * SEQ + l) * HDIM + d] = make_float2(v0, v1);
        }
    }
}

// ---------------------------------------------------------------------------
// Kernel 3: y = x + ctx @ out_w^T + out_b
// ---------------------------------------------------------------------------
__global__ __launch_bounds__(128) void out_mma_kernel(
    const float* __restrict__ x,
    const float* __restrict__ W,      // [256, 256]
    const float* __restrict__ bias)   // [256]
{
    __shared__ uint32_t As[64 * 64];
    __shared__ uint32_t Bs[64 * 64];

    const int n0 = blockIdx.x * 64;
    const int f0 = blockIdx.y * 64;
    const int tid = threadIdx.x;
    const int wid = tid >> 5;
    const int lane = tid & 31;
    const int g = lane >> 2;
    const int t = lane & 3;

    MmaTile acc;
    gemm_mainloop(g_ctx, NTOK, W, n0, f0, tid, wid, g, t, As, Bs, acc);

    const int r0 = n0 + 16 * wid + g;
    const int r1 = r0 + 8;
#pragma unroll
    for (int half = 0; half < 2; half++) {
        int n = half ? r1 : r0;
        if (n >= NTOK) continue;
#pragma unroll
        for (int nn = 0; nn < 8; nn++) {
            int f = f0 + 8 * nn + 2 * t;
            float2 xr = *(const float2*)&x[(size_t)n * 256 + f];
            float v0 = (half ? acc.C[nn][2] : acc.C[nn][0]) + bias[f]     + xr.x;
            float v1 = (half ? acc.C[nn][3] : acc.C[nn][1]) + bias[f + 1] + xr.y;
            *(float2*)&g_y[(size_t)n * 256 + f] = make_float2(v0, v1);
        }
    }
}

// ---------------------------------------------------------------------------
// Kernel 2: flash attention with tf32 warp MMA (unchanged from R3).
// ---------------------------------------------------------------------------
__global__ __launch_bounds__(128) void attn_mma_kernel()
{
    const int bh  = blockIdx.y;
    const int l0  = blockIdx.x * 64;
    const int wid = threadIdx.x >> 5;
    const int lane = threadIdx.x & 31;
    const int g = lane >> 2;
    const int t = lane & 3;
    const int r_lo = l0 + wid * 16 + g;
    const int r_hi = r_lo + 8;

    const float* __restrict__ qb = g_q + (size_t)bh * SEQ * HDIM;
    const float* __restrict__ kb = g_k + (size_t)bh * SEQ * HDIM;
    const float* __restrict__ vb = g_v + (size_t)bh * SEQ * HDIM;

    __shared__ uint32_t Ks[64 * 32];
    __shared__ uint32_t Vs[64 * 32];

    const float qscale = 0.17677669529663687f * 1.4426950408889634f;
    uint32_t Aq[4][4];
#pragma unroll
    for (int s = 0; s < 4; s++) {
        float q00 = 0.f, q10 = 0.f, q01 = 0.f, q11 = 0.f;
        if (r_lo < SEQ) {
            q00 = qb[r_lo * HDIM + 8 * s + t];
            q01 = qb[r_lo * HDIM + 8 * s + t + 4];
        }
        if (r_hi < SEQ) {
            q10 = qb[r_hi * HDIM + 8 * s + t];
            q11 = qb[r_hi * HDIM + 8 * s + t + 4];
        }
        Aq[s][0] = f2tf32(q00 * qscale);
        Aq[s][1] = f2tf32(q10 * qscale);
        Aq[s][2] = f2tf32(q01 * qscale);
        Aq[s][3] = f2tf32(q11 * qscale);
    }

    float o[4][4];
#pragma unroll
    for (int nn = 0; nn < 4; nn++)
#pragma unroll
        for (int e = 0; e < 4; e++) o[nn][e] = 0.f;

    float m_lo = -INFINITY, m_hi = -INFINITY;
    float l_lo = 0.f, l_hi = 0.f;

    const int glo = (r_lo < PADSZ) ? (r_lo / GROUPSZ) : -1;
    const int ghi = (r_hi < PADSZ) ? (r_hi / GROUPSZ) : -1;
    const bool blk_has_pad = (l0 < PADSZ);
    const int gminb = l0 / GROUPSZ;
    const int gmaxb = (min(l0 + 63, PADSZ - 1)) / GROUPSZ;

    for (int m0 = 0; m0 < SEQ; m0 += 64) {
        bool needed = (m0 + 64 > PADSZ);
        if (!needed) {
            if (blk_has_pad) {
                int gt0 = m0 / GROUPSZ, gt1 = (m0 + 63) / GROUPSZ;
                needed = !(gmaxb < gt0 || gminb > gt1);
            }
        }
        if (!needed) continue;

        __syncthreads();
#pragma unroll
        for (int it = 0; it < 4; it++) {
            int chunk = threadIdx.x + it * 128;
            int row = chunk >> 3;
            int c4  = (chunk & 7) * 4;
            int m = m0 + row;
            float4 kv = make_float4(0.f, 0.f, 0.f, 0.f);
            float4 vv = make_float4(0.f, 0.f, 0.f, 0.f);
            if (m < SEQ) {
                kv = *(const float4*)&kb[m * HDIM + c4];
                vv = *(const float4*)&vb[m * HDIM + c4];
            }
            int off = row * 32 + (c4 ^ ((row & 7) << 2));
            Ks[off + 0] = f2tf32(kv.x); Ks[off + 1] = f2tf32(kv.y);
            Ks[off + 2] = f2tf32(kv.z); Ks[off + 3] = f2tf32(kv.w);
            Vs[off + 0] = f2tf32(vv.x); Vs[off + 1] = f2tf32(vv.y);
            Vs[off + 2] = f2tf32(vv.z); Vs[off + 3] = f2tf32(vv.w);
        }
        __syncthreads();

        float S[8][4];
#pragma unroll
        for (int j = 0; j < 8; j++) {
            S[j][0] = 0.f; S[j][1] = 0.f; S[j][2] = 0.f; S[j][3] = 0.f;
            int base = (8 * j + g) * 32;
            int swz = g << 2;
#pragma unroll
            for (int s = 0; s < 4; s++) {
                uint32_t b0 = Ks[base + ((8 * s + t) ^ swz)];
                uint32_t b1 = Ks[base + ((8 * s + t + 4) ^ swz)];
                mma_tf32(S[j][0], S[j][1], S[j][2], S[j][3],
                         Aq[s][0], Aq[s][1], Aq[s][2], Aq[s][3], b0, b1);
            }
        }

        float tmax_lo = -INFINITY, tmax_hi = -INFINITY;
#pragma unroll
        for (int j = 0; j < 8; j++) {
            int c0 = m0 + 8 * j + 2 * t;
            int c1 = c0 + 1;
            int mg0 = c0 / GROUPSZ;
            int mg1 = c1 / GROUPSZ;
            bool b0lo = (c0 >= SEQ) || (c0 < PADSZ && mg0 != glo);
            bool b1lo = (c1 >= SEQ) || (c1 < PADSZ && mg1 != glo);
            bool b0hi = (c0 >= SEQ) || (c0 < PADSZ && mg0 != ghi);
            bool b1hi = (c1 >= SEQ) || (c1 < PADSZ && mg1 != ghi);
            if (b0lo) S[j][0] = -INFINITY;
            if (b1lo) S[j][1] = -INFINITY;
            if (b0hi) S[j][2] = -INFINITY;
            if (b1hi) S[j][3] = -INFINITY;
            tmax_lo = fmaxf(tmax_lo, fmaxf(S[j][0], S[j][1]));
            tmax_hi = fmaxf(tmax_hi, fmaxf(S[j][2], S[j][3]));
        }
        tmax_lo = fmaxf(tmax_lo, __shfl_xor_sync(0xffffffffu, tmax_lo, 1));
        tmax_lo = fmaxf(tmax_lo, __shfl_xor_sync(0xffffffffu, tmax_lo, 2));
        tmax_hi = fmaxf(tmax_hi, __shfl_xor_sync(0xffffffffu, tmax_hi, 1));
        tmax_hi = fmaxf(tmax_hi, __shfl_xor_sync(0xffffffffu, tmax_hi, 2));

        float mnew_lo = fmaxf(m_lo, tmax_lo);
        float mnew_hi = fmaxf(m_hi, tmax_hi);
        float msafe_lo = (mnew_lo == -INFINITY) ? 0.f : mnew_lo;
        float msafe_hi = (mnew_hi == -INFINITY) ? 0.f : mnew_hi;
        float corr_lo = fast_exp2(m_lo - msafe_lo);
        float corr_hi = fast_exp2(m_hi - msafe_hi);
        m_lo = mnew_lo; m_hi = mnew_hi;

        l_lo *= corr_lo;
        l_hi *= corr_hi;
#pragma unroll
        for (int nn = 0; nn < 4; nn++) {
            o[nn][0] *= corr_lo; o[nn][1] *= corr_lo;
            o[nn][2] *= corr_hi; o[nn][3] *= corr_hi;
        }

#pragma unroll
        for (int j = 0; j < 8; j++) {
            S[j][0] = fast_exp2(S[j][0] - msafe_lo);
            S[j][1] = fast_exp2(S[j][1] - msafe_lo);
            S[j][2] = fast_exp2(S[j][2] - msafe_hi);
            S[j][3] = fast_exp2(S[j][3] - msafe_hi);
            l_lo += S[j][0] + S[j][1];
            l_hi += S[j][2] + S[j][3];
        }

#pragma unroll
        for (int c = 0; c < 8; c++) {
            int src0 = (lane & ~3) | (t >> 1);
            int src1 = (lane & ~3) | (2 + (t >> 1));
            float x0 = __shfl_sync(0xffffffffu, S[c][0], src0);
            float x1 = __shfl_sync(0xffffffffu, S[c][1], src0);
            float y0 = __shfl_sync(0xffffffffu, S[c][0], src1);
            float y1 = __shfl_sync(0xffffffffu, S[c][1], src1);
            float z0 = __shfl_sync(0xffffffffu, S[c][2], src0);
            float z1 = __shfl_sync(0xffffffffu, S[c][3], src0);
            float w0 = __shfl_sync(0xffffffffu, S[c][2], src1);
            float w1 = __shfl_sync(0xffffffffu, S[c][3], src1);
            bool odd = (t & 1);
            uint32_t a0 = f2tf32(odd ? x1 : x0);
            uint32_t a1 = f2tf32(odd ? z1 : z0);
            uint32_t a2 = f2tf32(odd ? y1 : y0);
            uint32_t a3 = f2tf32(odd ? w1 : w0);

            int base0 = (8 * c + t) * 32;
            int base1 = (8 * c + t + 4) * 32;
            int swz0 = t << 2;
            int swz1 = (t + 4) << 2;
#pragma unroll
            for (int nn = 0; nn < 4; nn++) {
                uint32_t b0 = Vs[base0 + ((8 * nn + g) ^ swz0)];
                uint32_t b1 = Vs[base1 + ((8 * nn + g) ^ swz1)];
                mma_tf32(o[nn][0], o[nn][1], o[nn][2], o[nn][3],
                         a0, a1, a2, a3, b0, b1);
            }
        }
    }

    l_lo += __shfl_xor_sync(0xffffffffu, l_lo, 1);
    l_lo += __shfl_xor_sync(0xffffffffu, l_lo, 2);
    l_hi += __shfl_xor_sync(0xffffffffu, l_hi, 1);
    l_hi += __shfl_xor_sync(0xffffffffu, l_hi, 2);
    float inv_lo = 1.0f / l_lo;
    float inv_hi = 1.0f / l_hi;

    const int b = bh >> 3;
    const int h = bh & 7;
    if (r_lo < SEQ) {
        float* dst = &g_ctx[((size_t)b * SEQ + r_lo) * EMB + h * HDIM];
#pragma unroll
        for (int nn = 0; nn < 4; nn++)
            *(float2*)&dst[8 * nn + 2 * t] = make_float2(o[nn][0] * inv_lo, o[nn][1] * inv_lo);
    }
    if (r_hi < SEQ) {
        float* dst = &g_ctx[((size_t)b * SEQ + r_hi) * EMB + h * HDIM];
#pragma unroll
        for (int nn = 0; nn < 4; nn++)
            *(float2*)&dst[8 * nn + 2 * t] = make_float2(o[nn][2] * inv_hi, o[nn][3] * inv_hi);
    }
}

// ---------------------------------------------------------------------------
// Kernel 4: row LayerNorm
// ---------------------------------------------------------------------------
__global__ __launch_bounds__(256) void ln_kernel(
    const float* __restrict__ gamma,
    const float* __restrict__ beta,
    float* __restrict__ out)
{
    const int n = blockIdx.x;
    const int f = threadIdx.x;
    float v = g_y[n * 256 + f];

    float s1 = v, s2 = v * v;
#pragma unroll
    for (int off = 16; off > 0; off >>= 1) {
        s1 += __shfl_xor_sync(0xffffffffu, s1, off);
        s2 += __shfl_xor_sync(0xffffffffu, s2, off);
    }
    __shared__ float a1[8], a2[8];
    int w = f >> 5, ln = f & 31;
    if (ln == 0) { a1[w] = s1; a2[w] = s2; }
    __syncthreads();
    float S1 = 0.f, S2 = 0.f;
#pragma unroll
    for (int i = 0; i < 8; i++) { S1 += a1[i]; S2 += a2[i]; }

    float mean = S1 * (1.0f / 256.0f);
    float var  = S2 * (1.0f / 256.0f) - mean * mean;
    float r = rsqrtf(var + LNEPS);
    out[n * 256 + f] = (v - mean) * r * gamma[f] + beta[f];
}

// ---------------------------------------------------------------------------
extern "C" void kernel_launch(void* const* d_in, const int* in_sizes, int n_in,
                              void* d_out, int out_size)
{
    const float* x     = (const float*)d_in[0];
    const float* in_w  = (const float*)d_in[1];
    const float* in_b  = (const float*)d_in[2];
    const float* out_w = (const float*)d_in[3];
    const float* out_b = (const float*)d_in[4];
    const float* ln_g  = (const float*)d_in[5];
    const float* ln_b  = (const float*)d_in[6];
    float* out = (float*)d_out;

    qkv_mma_kernel<<<dim3((NTOK + 63) / 64, F3 / 64), 128>>>(x, in_w, in_b);
    attn_mma_kernel<<<dim3((SEQ + 63) / 64, BATCH * NHEAD), 128>>>();
    out_mma_kernel<<<dim3((NTOK + 63) / 64, EMB / 64), 128>>>(x, out_w, out_b);
    ln_kernel<<<NTOK, 256>>>(ln_g, ln_b, out);
}

// round 8
// speedup vs baseline: 3.5520x; 1.1066x over previous
#include <cuda_runtime.h>
#include <math.h>
#include <stdint.h>

#define BATCH 8
#define SEQ 1900
#define EMB 256
#define NHEAD 8
#define HDIM 32
#define NTOK (BATCH*SEQ)        // 15200
#define F3 (3*EMB)              // 768
#define PADSZ 1000
#define GROUPSZ 200
#define LNEPS 1e-5f

// ---------------- scratch (device globals, no allocations) ----------------
__device__ __align__(16) float g_q[BATCH*NHEAD*SEQ*HDIM];
__device__ __align__(16) float g_k[BATCH*NHEAD*SEQ*HDIM];
__device__ __align__(16) float g_v[BATCH*NHEAD*SEQ*HDIM];
__device__ __align__(16) float g_ctx[NTOK*EMB];
__device__ __align__(16) float g_y[NTOK*EMB];

__device__ __forceinline__ float fast_exp2(float x) {
    float y;
    asm("ex2.approx.ftz.f32 %0, %1;" : "=f"(y) : "f"(x));
    return y;
}

__device__ __forceinline__ uint32_t f2tf32(float f) {
    uint32_t u;
    asm("cvt.rna.tf32.f32 %0, %1;" : "=r"(u) : "f"(f));
    return u;
}

__device__ __forceinline__ void mma_tf32(float& c0, float& c1, float& c2, float& c3,
                                         uint32_t a0, uint32_t a1, uint32_t a2, uint32_t a3,
                                         uint32_t b0, uint32_t b1) {
    asm volatile(
        "mma.sync.aligned.m16n8k8.row.col.f32.tf32.tf32.f32 "
        "{%0,%1,%2,%3}, {%4,%5,%6,%7}, {%8,%9}, {%0,%1,%2,%3};"
        : "+f"(c0), "+f"(c1), "+f"(c2), "+f"(c3)
        : "r"(a0), "r"(a1), "r"(a2), "r"(a3), "r"(b0), "r"(b1));
}

__device__ __forceinline__ void cp_async16(uint32_t smem_addr, const void* gsrc, uint32_t src_bytes) {
    asm volatile("cp.async.cg.shared.global [%0], [%1], 16, %2;\n"
                 :: "r"(smem_addr), "l"(gsrc), "r"(src_bytes));
}
__device__ __forceinline__ void cp_commit() {
    asm volatile("cp.async.commit_group;\n");
}
template <int N>
__device__ __forceinline__ void cp_wait() {
    asm volatile("cp.async.wait_group %0;\n" :: "n"(N));
}

// ===========================================================================
// tf32 MMA GEMM core: out[n,f] = sum_k A[n,k] * W[f,k]
// Block: 128 threads (4 warps). Tile: 128(M) x 64(N), BK=32, K=256.
// cp.async double-buffered. Warp w computes rows [32w, 32w+32) x 64 cols.
// Smem rows XOR-swizzled (32 cols, 128B) -> conflict-free LDS.
// ===========================================================================
struct Acc {
    float C[8][2][4];   // [nn 8][row-block 2][c-frag 4]
};

__device__ __forceinline__ void gemm_mainloop_128(
    const float* __restrict__ A, int a_rows,
    const float* __restrict__ W,
    int n0, int f0, int tid, int wid, int g, int t,
    uint32_t* As, uint32_t* Bs, Acc& acc)   // As: 2 x 128x32, Bs: 2 x 64x32
{
#pragma unroll
    for (int nn = 0; nn < 8; nn++)
#pragma unroll
        for (int b = 0; b < 2; b++)
#pragma unroll
            for (int e = 0; e < 4; e++) acc.C[nn][b][e] = 0.f;

    const uint32_t as_base = (uint32_t)__cvta_generic_to_shared(As);
    const uint32_t bs_base = (uint32_t)__cvta_generic_to_shared(Bs);
    const int sw = g << 2;
    const int rw = 32 * wid;

    // stage loader
    auto load_stage = [&](int kc, int stage) {
        int k0 = kc * 32;
        uint32_t a_st = as_base + stage * (128 * 32 * 4);
        uint32_t b_st = bs_base + stage * (64 * 32 * 4);
        // A: 128x32 floats = 1024 float4, 8 per thread
#pragma unroll
        for (int i = 0; i < 8; i++) {
            int idx = tid + i * 128;
            int row = idx >> 3;
            int c4  = (idx & 7) * 4;
            int off = row * 32 + (c4 ^ ((row & 7) << 2));
            int gn = n0 + row;
            bool ok = (gn < a_rows);
            const float* src = A + (size_t)(ok ? gn : 0) * 256 + k0 + c4;
            cp_async16(a_st + off * 4, src, ok ? 16u : 0u);
        }
        // B: 64x32 floats = 512 float4, 4 per thread
#pragma unroll
        for (int i = 0; i < 4; i++) {
            int idx = tid + i * 128;
            int row = idx >> 3;
            int c4  = (idx & 7) * 4;
            int off = row * 32 + (c4 ^ ((row & 7) << 2));
            const float* src = W + (size_t)(f0 + row) * 256 + k0 + c4;
            cp_async16(b_st + off * 4, src, 16u);
        }
        cp_commit();
    };

    load_stage(0, 0);

    for (int kc = 0; kc < 8; kc++) {
        int buf = kc & 1;
        if (kc + 1 < 8) {
            load_stage(kc + 1, buf ^ 1);
            cp_wait<1>();
        } else {
            cp_wait<0>();
        }
        __syncthreads();

        const uint32_t* as = As + buf * (128 * 32);
        const uint32_t* bs = Bs + buf * (64 * 32);

#pragma unroll
        for (int s = 0; s < 4; s++) {
            int kl = 8 * s + t;
            int kh = kl + 4;
            // A fragments: rows rw+g, +8, +16, +24 (all have (row&7)==g)
            uint32_t a00 = as[(rw + g)      * 32 + (kl ^ sw)];
            uint32_t a01 = as[(rw + g + 8)  * 32 + (kl ^ sw)];
            uint32_t a02 = as[(rw + g)      * 32 + (kh ^ sw)];
            uint32_t a03 = as[(rw + g + 8)  * 32 + (kh ^ sw)];
            uint32_t a10 = as[(rw + g + 16) * 32 + (kl ^ sw)];
            uint32_t a11 = as[(rw + g + 24) * 32 + (kl ^ sw)];
            uint32_t a12 = as[(rw + g + 16) * 32 + (kh ^ sw)];
            uint32_t a13 = as[(rw + g + 24) * 32 + (kh ^ sw)];
#pragma unroll
            for (int nn = 0; nn < 8; nn++) {
                int fr = 8 * nn + g;
                uint32_t b0 = bs[fr * 32 + (kl ^ sw)];
                uint32_t b1 = bs[fr * 32 + (kh ^ sw)];
                mma_tf32(acc.C[nn][0][0], acc.C[nn][0][1], acc.C[nn][0][2], acc.C[nn][0][3],
                         a00, a01, a02, a03, b0, b1);
                mma_tf32(acc.C[nn][1][0], acc.C[nn][1][1], acc.C[nn][1][2], acc.C[nn][1][3],
                         a10, a11, a12, a13, b0, b1);
            }
        }
        __syncthreads();
    }
}

// ---------------------------------------------------------------------------
// Kernel 1: QKV = x @ W^T + b, scattered to q/k/v [B,H,L,D]
// ---------------------------------------------------------------------------
__global__ __launch_bounds__(128) void qkv_mma_kernel(
    const float* __restrict__ x,
    const float* __restrict__ W,
    const float* __restrict__ bias)
{
    __shared__ __align__(16) uint32_t As[2 * 128 * 32];
    __shared__ __align__(16) uint32_t Bs[2 * 64 * 32];

    const int n0 = blockIdx.x * 128;
    const int f0 = blockIdx.y * 64;
    const int tid = threadIdx.x;
    const int wid = tid >> 5;
    const int lane = tid & 31;
    const int g = lane >> 2;
    const int t = lane & 3;

    Acc acc;
    gemm_mainloop_128(x, NTOK, W, n0, f0, tid, wid, g, t, As, Bs, acc);

#pragma unroll
    for (int blk = 0; blk < 2; blk++) {
#pragma unroll
        for (int half = 0; half < 2; half++) {
            int n = n0 + 32 * wid + 16 * blk + 8 * half + g;
            if (n >= NTOK) continue;
            int b = n / SEQ;
            int l = n % SEQ;
#pragma unroll
            for (int nn = 0; nn < 8; nn++) {
                int f = f0 + 8 * nn + 2 * t;
                float v0 = acc.C[nn][blk][2 * half]     + bias[f];
                float v1 = acc.C[nn][blk][2 * half + 1] + bias[f + 1];
                int which = f >> 8;
                int e = f & 255;
                int h = e >> 5;
                int d = e & 31;
                float* dst = (which == 0) ? g_q : ((which == 1) ? g_k : g_v);
                *(float2*)&dst[(((b * NHEAD) + h) * SEQ + l) * HDIM + d] = make_float2(v0, v1);
            }
        }
    }
}

// ---------------------------------------------------------------------------
// Kernel 3: y = x + ctx @ out_w^T + out_b
// ---------------------------------------------------------------------------
__global__ __launch_bounds__(128) void out_mma_kernel(
    const float* __restrict__ x,
    const float* __restrict__ W,
    const float* __restrict__ bias)
{
    __shared__ __align__(16) uint32_t As[2 * 128 * 32];
    __shared__ __align__(16) uint32_t Bs[2 * 64 * 32];

    const int n0 = blockIdx.x * 128;
    const int f0 = blockIdx.y * 64;
    const int tid = threadIdx.x;
    const int wid = tid >> 5;
    const int lane = tid & 31;
    const int g = lane >> 2;
    const int t = lane & 3;

    Acc acc;
    gemm_mainloop_128(g_ctx, NTOK, W, n0, f0, tid, wid, g, t, As, Bs, acc);

#pragma unroll
    for (int blk = 0; blk < 2; blk++) {
#pragma unroll
        for (int half = 0; half < 2; half++) {
            int n = n0 + 32 * wid + 16 * blk + 8 * half + g;
            if (n >= NTOK) continue;
#pragma unroll
            for (int nn = 0; nn < 8; nn++) {
                int f = f0 + 8 * nn + 2 * t;
                float2 xr = *(const float2*)&x[(size_t)n * 256 + f];
                float v0 = acc.C[nn][blk][2 * half]     + bias[f]     + xr.x;
                float v1 = acc.C[nn][blk][2 * half + 1] + bias[f + 1] + xr.y;
                *(float2*)&g_y[(size_t)n * 256 + f] = make_float2(v0, v1);
            }
        }
    }
}

// ---------------------------------------------------------------------------
// Kernel 2: flash attention, tf32 warp MMA (unchanged)
// ---------------------------------------------------------------------------
__global__ __launch_bounds__(128) void attn_mma_kernel()
{
    const int bh  = blockIdx.y;
    const int l0  = blockIdx.x * 64;
    const int wid = threadIdx.x >> 5;
    const int lane = threadIdx.x & 31;
    const int g = lane >> 2;
    const int t = lane & 3;
    const int r_lo = l0 + wid * 16 + g;
    const int r_hi = r_lo + 8;

    const float* __restrict__ qb = g_q + (size_t)bh * SEQ * HDIM;
    const float* __restrict__ kb = g_k + (size_t)bh * SEQ * HDIM;
    const float* __restrict__ vb = g_v + (size_t)bh * SEQ * HDIM;

    __shared__ uint32_t Ks[64 * 32];
    __shared__ uint32_t Vs[64 * 32];

    const float qscale = 0.17677669529663687f * 1.4426950408889634f;
    uint32_t Aq[4][4];
#pragma unroll
    for (int s = 0; s < 4; s++) {
        float q00 = 0.f, q10 = 0.f, q01 = 0.f, q11 = 0.f;
        if (r_lo < SEQ) {
            q00 = qb[r_lo * HDIM + 8 * s + t];
            q01 = qb[r_lo * HDIM + 8 * s + t + 4];
        }
        if (r_hi < SEQ) {
            q10 = qb[r_hi * HDIM + 8 * s + t];
            q11 = qb[r_hi * HDIM + 8 * s + t + 4];
        }
        Aq[s][0] = f2tf32(q00 * qscale);
        Aq[s][1] = f2tf32(q10 * qscale);
        Aq[s][2] = f2tf32(q01 * qscale);
        Aq[s][3] = f2tf32(q11 * qscale);
    }

    float o[4][4];
#pragma unroll
    for (int nn = 0; nn < 4; nn++)
#pragma unroll
        for (int e = 0; e < 4; e++) o[nn][e] = 0.f;

    float m_lo = -INFINITY, m_hi = -INFINITY;
    float l_lo = 0.f, l_hi = 0.f;

    const int glo = (r_lo < PADSZ) ? (r_lo / GROUPSZ) : -1;
    const int ghi = (r_hi < PADSZ) ? (r_hi / GROUPSZ) : -1;
    const bool blk_has_pad = (l0 < PADSZ);
    const int gminb = l0 / GROUPSZ;
    const int gmaxb = (min(l0 + 63, PADSZ - 1)) / GROUPSZ;

    for (int m0 = 0; m0 < SEQ; m0 += 64) {
        bool needed = (m0 + 64 > PADSZ);
        if (!needed) {
            if (blk_has_pad) {
                int gt0 = m0 / GROUPSZ, gt1 = (m0 + 63) / GROUPSZ;
                needed = !(gmaxb < gt0 || gminb > gt1);
            }
        }
        if (!needed) continue;

        __syncthreads();
#pragma unroll
        for (int it = 0; it < 4; it++) {
            int chunk = threadIdx.x + it * 128;
            int row = chunk >> 3;
            int c4  = (chunk & 7) * 4;
            int m = m0 + row;
            float4 kv = make_float4(0.f, 0.f, 0.f, 0.f);
            float4 vv = make_float4(0.f, 0.f, 0.f, 0.f);
            if (m < SEQ) {
                kv = *(const float4*)&kb[m * HDIM + c4];
                vv = *(const float4*)&vb[m * HDIM + c4];
            }
            int off = row * 32 + (c4 ^ ((row & 7) << 2));
            Ks[off + 0] = f2tf32(kv.x); Ks[off + 1] = f2tf32(kv.y);
            Ks[off + 2] = f2tf32(kv.z); Ks[off + 3] = f2tf32(kv.w);
            Vs[off + 0] = f2tf32(vv.x); Vs[off + 1] = f2tf32(vv.y);
            Vs[off + 2] = f2tf32(vv.z); Vs[off + 3] = f2tf32(vv.w);
        }
        __syncthreads();

        float S[8][4];
#pragma unroll
        for (int j = 0; j < 8; j++) {
            S[j][0] = 0.f; S[j][1] = 0.f; S[j][2] = 0.f; S[j][3] = 0.f;
            int base = (8 * j + g) * 32;
            int swz = g << 2;
#pragma unroll
            for (int s = 0; s < 4; s++) {
                uint32_t b0 = Ks[base + ((8 * s + t) ^ swz)];
                uint32_t b1 = Ks[base + ((8 * s + t + 4) ^ swz)];
                mma_tf32(S[j][0], S[j][1], S[j][2], S[j][3],
                         Aq[s][0], Aq[s][1], Aq[s][2], Aq[s][3], b0, b1);
            }
        }

        float tmax_lo = -INFINITY, tmax_hi = -INFINITY;
#pragma unroll
        for (int j = 0; j < 8; j++) {
            int c0 = m0 + 8 * j + 2 * t;
            int c1 = c0 + 1;
            int mg0 = c0 / GROUPSZ;
            int mg1 = c1 / GROUPSZ;
            bool b0lo = (c0 >= SEQ) || (c0 < PADSZ && mg0 != glo);
            bool b1lo = (c1 >= SEQ) || (c1 < PADSZ && mg1 != glo);
            bool b0hi = (c0 >= SEQ) || (c0 < PADSZ && mg0 != ghi);
            bool b1hi = (c1 >= SEQ) || (c1 < PADSZ && mg1 != ghi);
            if (b0lo) S[j][0] = -INFINITY;
            if (b1lo) S[j][1] = -INFINITY;
            if (b0hi) S[j][2] = -INFINITY;
            if (b1hi) S[j][3] = -INFINITY;
            tmax_lo = fmaxf(tmax_lo, fmaxf(S[j][0], S[j][1]));
            tmax_hi = fmaxf(tmax_hi, fmaxf(S[j][2], S[j][3]));
        }
        tmax_lo = fmaxf(tmax_lo, __shfl_xor_sync(0xffffffffu, tmax_lo, 1));
        tmax_lo = fmaxf(tmax_lo, __shfl_xor_sync(0xffffffffu, tmax_lo, 2));
        tmax_hi = fmaxf(tmax_hi, __shfl_xor_sync(0xffffffffu, tmax_hi, 1));
        tmax_hi = fmaxf(tmax_hi, __shfl_xor_sync(0xffffffffu, tmax_hi, 2));

        float mnew_lo = fmaxf(m_lo, tmax_lo);
        float mnew_hi = fmaxf(m_hi, tmax_hi);
        float msafe_lo = (mnew_lo == -INFINITY) ? 0.f : mnew_lo;
        float msafe_hi = (mnew_hi == -INFINITY) ? 0.f : mnew_hi;
        float corr_lo = fast_exp2(m_lo - msafe_lo);
        float corr_hi = fast_exp2(m_hi - msafe_hi);
        m_lo = mnew_lo; m_hi = mnew_hi;

        l_lo *= corr_lo;
        l_hi *= corr_hi;
#pragma unroll
        for (int nn = 0; nn < 4; nn++) {
            o[nn][0] *= corr_lo; o[nn][1] *= corr_lo;
            o[nn][2] *= corr_hi; o[nn][3] *= corr_hi;
        }

#pragma unroll
        for (int j = 0; j < 8; j++) {
            S[j][0] = fast_exp2(S[j][0] - msafe_lo);
            S[j][1] = fast_exp2(S[j][1] - msafe_lo);
            S[j][2] = fast_exp2(S[j][2] - msafe_hi);
            S[j][3] = fast_exp2(S[j][3] - msafe_hi);
            l_lo += S[j][0] + S[j][1];
            l_hi += S[j][2] + S[j][3];
        }

#pragma unroll
        for (int c = 0; c < 8; c++) {
            int src0 = (lane & ~3) | (t >> 1);
            int src1 = (lane & ~3) | (2 + (t >> 1));
            float x0 = __shfl_sync(0xffffffffu, S[c][0], src0);
            float x1 = __shfl_sync(0xffffffffu, S[c][1], src0);
            float y0 = __shfl_sync(0xffffffffu, S[c][0], src1);
            float y1 = __shfl_sync(0xffffffffu, S[c][1], src1);
            float z0 = __shfl_sync(0xffffffffu, S[c][2], src0);
            float z1 = __shfl_sync(0xffffffffu, S[c][3], src0);
            float w0 = __shfl_sync(0xffffffffu, S[c][2], src1);
            float w1 = __shfl_sync(0xffffffffu, S[c][3], src1);
            bool odd = (t & 1);
            uint32_t a0 = f2tf32(odd ? x1 : x0);
            uint32_t a1 = f2tf32(odd ? z1 : z0);
            uint32_t a2 = f2tf32(odd ? y1 : y0);
            uint32_t a3 = f2tf32(odd ? w1 : w0);

            int base0 = (8 * c + t) * 32;
            int base1 = (8 * c + t + 4) * 32;
            int swz0 = t << 2;
            int swz1 = (t + 4) << 2;
#pragma unroll
            for (int nn = 0; nn < 4; nn++) {
                uint32_t b0 = Vs[base0 + ((8 * nn + g) ^ swz0)];
                uint32_t b1 = Vs[base1 + ((8 * nn + g) ^ swz1)];
                mma_tf32(o[nn][0], o[nn][1], o[nn][2], o[nn][3],
                         a0, a1, a2, a3, b0, b1);
            }
        }
    }

    l_lo += __shfl_xor_sync(0xffffffffu, l_lo, 1);
    l_lo += __shfl_xor_sync(0xffffffffu, l_lo, 2);
    l_hi += __shfl_xor_sync(0xffffffffu, l_hi, 1);
    l_hi += __shfl_xor_sync(0xffffffffu, l_hi, 2);
    float inv_lo = 1.0f / l_lo;
    float inv_hi = 1.0f / l_hi;

    const int b = bh >> 3;
    const int h = bh & 7;
    if (r_lo < SEQ) {
        float* dst = &g_ctx[((size_t)b * SEQ + r_lo) * EMB + h * HDIM];
#pragma unroll
        for (int nn = 0; nn < 4; nn++)
            *(float2*)&dst[8 * nn + 2 * t] = make_float2(o[nn][0] * inv_lo, o[nn][1] * inv_lo);
    }
    if (r_hi < SEQ) {
        float* dst = &g_ctx[((size_t)b * SEQ + r_hi) * EMB + h * HDIM];
#pragma unroll
        for (int nn = 0; nn < 4; nn++)
            *(float2*)&dst[8 * nn + 2 * t] = make_float2(o[nn][2] * inv_hi, o[nn][3] * inv_hi);
    }
}

// ---------------------------------------------------------------------------
// Kernel 4: row LayerNorm
// ---------------------------------------------------------------------------
__global__ __launch_bounds__(256) void ln_kernel(
    const float* __restrict__ gamma,
    const float* __restrict__ beta,
    float* __restrict__ out)
{
    const int n = blockIdx.x;
    const int f = threadIdx.x;
    float v = g_y[n * 256 + f];

    float s1 = v, s2 = v * v;
#pragma unroll
    for (int off = 16; off > 0; off >>= 1) {
        s1 += __shfl_xor_sync(0xffffffffu, s1, off);
        s2 += __shfl_xor_sync(0xffffffffu, s2, off);
    }
    __shared__ float a1[8], a2[8];
    int w = f >> 5, ln = f & 31;
    if (ln == 0) { a1[w] = s1; a2[w] = s2; }
    __syncthreads();
    float S1 = 0.f, S2 = 0.f;
#pragma unroll
    for (int i = 0; i < 8; i++) { S1 += a1[i]; S2 += a2[i]; }

    float mean = S1 * (1.0f / 256.0f);
    float var  = S2 * (1.0f / 256.0f) - mean * mean;
    float r = rsqrtf(var + LNEPS);
    out[n * 256 + f] = (v - mean) * r * gamma[f] + beta[f];
}

// ---------------------------------------------------------------------------
extern "C" void kernel_launch(void* const* d_in, const int* in_sizes, int n_in,
                              void* d_out, int out_size)
{
    const float* x     = (const float*)d_in[0];
    const float* in_w  = (const float*)d_in[1];
    const float* in_b  = (const float*)d_in[2];
    const float* out_w = (const float*)d_in[3];
    const float* out_b = (const float*)d_in[4];
    const float* ln_g  = (const float*)d_in[5];
    const float* ln_b  = (const float*)d_in[6];
    float* out = (float*)d_out;

    qkv_mma_kernel<<<dim3((NTOK + 127) / 128, F3 / 64), 128>>>(x, in_w, in_b);
    attn_mma_kernel<<<dim3((SEQ + 63) / 64, BATCH * NHEAD), 128>>>();
    out_mma_kernel<<<dim3((NTOK + 127) / 128, EMB / 64), 128>>>(x, out_w, out_b);
    ln_kernel<<<NTOK, 256>>>(ln_g, ln_b, out);
}

// round 9
// speedup vs baseline: 4.6122x; 1.2985x over previous
#include <cuda_runtime.h>
#include <cuda_fp16.h>
#include <math.h>
#include <stdint.h>

#define BATCH 8
#define SEQ 1900
#define SEQP 1904              // padded for 16B-aligned g_vt rows
#define EMB 256
#define NHEAD 8
#define HDIM 32
#define NTOK (BATCH*SEQ)       // 15200
#define F3 (3*EMB)             // 768
#define PADSZ 1000
#define GROUPSZ 200
#define LNEPS 1e-5f

// ---------------- scratch (device globals, no allocations) ----------------
// q (prescaled, fp16 packed as half2 words), k (fp16), v transposed (fp16)
__device__ __align__(16) uint32_t g_qh[BATCH*NHEAD*SEQ*16];     // [bh][l][16 words]
__device__ __align__(16) uint32_t g_kh[BATCH*NHEAD*SEQ*16];     // [bh][l][16 words]
__device__ __align__(16) __half   g_vt[BATCH*NHEAD*HDIM*SEQP];  // [bh][d][l]
__device__ __align__(16) float    g_ctx[NTOK*EMB];

__device__ __forceinline__ float fast_exp2(float x) {
    float y;
    asm("ex2.approx.ftz.f32 %0, %1;" : "=f"(y) : "f"(x));
    return y;
}

__device__ __forceinline__ uint32_t h2pack(float a, float b) {
    __half2 h = __floats2half2_rn(a, b);
    return *(uint32_t*)&h;
}

__device__ __forceinline__ void mma_tf32(float& c0, float& c1, float& c2, float& c3,
                                         uint32_t a0, uint32_t a1, uint32_t a2, uint32_t a3,
                                         uint32_t b0, uint32_t b1) {
    asm volatile(
        "mma.sync.aligned.m16n8k8.row.col.f32.tf32.tf32.f32 "
        "{%0,%1,%2,%3}, {%4,%5,%6,%7}, {%8,%9}, {%0,%1,%2,%3};"
        : "+f"(c0), "+f"(c1), "+f"(c2), "+f"(c3)
        : "r"(a0), "r"(a1), "r"(a2), "r"(a3), "r"(b0), "r"(b1));
}

__device__ __forceinline__ void mma_f16(float& c0, float& c1, float& c2, float& c3,
                                        uint32_t a0, uint32_t a1, uint32_t a2, uint32_t a3,
                                        uint32_t b0, uint32_t b1) {
    asm volatile(
        "mma.sync.aligned.m16n8k16.row.col.f32.f16.f16.f32 "
        "{%0,%1,%2,%3}, {%4,%5,%6,%7}, {%8,%9}, {%0,%1,%2,%3};"
        : "+f"(c0), "+f"(c1), "+f"(c2), "+f"(c3)
        : "r"(a0), "r"(a1), "r"(a2), "r"(a3), "r"(b0), "r"(b1));
}

__device__ __forceinline__ void cp_async16(uint32_t smem_addr, const void* gsrc, uint32_t src_bytes) {
    asm volatile("cp.async.cg.shared.global [%0], [%1], 16, %2;\n"
                 :: "r"(smem_addr), "l"(gsrc), "r"(src_bytes));
}
__device__ __forceinline__ void cp_commit() {
    asm volatile("cp.async.commit_group;\n");
}
template <int N>
__device__ __forceinline__ void cp_wait() {
    asm volatile("cp.async.wait_group %0;\n" :: "n"(N));
}

// ===========================================================================
// Kernel 1: QKV = x @ W^T + b  (tf32 MMA, BM=128 BN=64 BK=32, cp.async x2)
// Epilogue: q -> fp16 (prescaled), k -> fp16, v -> fp16 transposed [bh][d][l]
// ===========================================================================
__global__ __launch_bounds__(128) void qkv_mma_kernel(
    const float* __restrict__ x,
    const float* __restrict__ W,
    const float* __restrict__ bias)
{
    __shared__ __align__(16) uint32_t As[2 * 128 * 32];
    __shared__ __align__(16) uint32_t Bs[2 * 64 * 32];

    const int n0 = blockIdx.x * 128;
    const int f0 = blockIdx.y * 64;
    const int tid = threadIdx.x;
    const int wid = tid >> 5;
    const int lane = tid & 31;
    const int g = lane >> 2;
    const int t = lane & 3;

    float C[8][2][4];
#pragma unroll
    for (int nn = 0; nn < 8; nn++)
#pragma unroll
        for (int b = 0; b < 2; b++)
#pragma unroll
            for (int e = 0; e < 4; e++) C[nn][b][e] = 0.f;

    const uint32_t as_base = (uint32_t)__cvta_generic_to_shared(As);
    const uint32_t bs_base = (uint32_t)__cvta_generic_to_shared(Bs);
    const int sw = g << 2;
    const int rw = 32 * wid;

    auto load_stage = [&](int kc, int stage) {
        int k0 = kc * 32;
        uint32_t a_st = as_base + stage * (128 * 32 * 4);
        uint32_t b_st = bs_base + stage * (64 * 32 * 4);
#pragma unroll
        for (int i = 0; i < 8; i++) {
            int idx = tid + i * 128;
            int row = idx >> 3;
            int c4  = (idx & 7) * 4;
            int off = row * 32 + (c4 ^ ((row & 7) << 2));
            int gn = n0 + row;
            bool ok = (gn < NTOK);
            const float* src = x + (size_t)(ok ? gn : 0) * 256 + k0 + c4;
            cp_async16(a_st + off * 4, src, ok ? 16u : 0u);
        }
#pragma unroll
        for (int i = 0; i < 4; i++) {
            int idx = tid + i * 128;
            int row = idx >> 3;
            int c4  = (idx & 7) * 4;
            int off = row * 32 + (c4 ^ ((row & 7) << 2));
            const float* src = W + (size_t)(f0 + row) * 256 + k0 + c4;
            cp_async16(b_st + off * 4, src, 16u);
        }
        cp_commit();
    };

    load_stage(0, 0);

    for (int kc = 0; kc < 8; kc++) {
        int buf = kc & 1;
        if (kc + 1 < 8) { load_stage(kc + 1, buf ^ 1); cp_wait<1>(); }
        else           { cp_wait<0>(); }
        __syncthreads();

        const uint32_t* as = As + buf * (128 * 32);
        const uint32_t* bs = Bs + buf * (64 * 32);

#pragma unroll
        for (int s = 0; s < 4; s++) {
            int kl = 8 * s + t;
            int kh = kl + 4;
            uint32_t a00 = as[(rw + g)      * 32 + (kl ^ sw)];
            uint32_t a01 = as[(rw + g + 8)  * 32 + (kl ^ sw)];
            uint32_t a02 = as[(rw + g)      * 32 + (kh ^ sw)];
            uint32_t a03 = as[(rw + g + 8)  * 32 + (kh ^ sw)];
            uint32_t a10 = as[(rw + g + 16) * 32 + (kl ^ sw)];
            uint32_t a11 = as[(rw + g + 24) * 32 + (kl ^ sw)];
            uint32_t a12 = as[(rw + g + 16) * 32 + (kh ^ sw)];
            uint32_t a13 = as[(rw + g + 24) * 32 + (kh ^ sw)];
#pragma unroll
            for (int nn = 0; nn < 8; nn++) {
                int fr = 8 * nn + g;
                uint32_t b0 = bs[fr * 32 + (kl ^ sw)];
                uint32_t b1 = bs[fr * 32 + (kh ^ sw)];
                mma_tf32(C[nn][0][0], C[nn][0][1], C[nn][0][2], C[nn][0][3],
                         a00, a01, a02, a03, b0, b1);
                mma_tf32(C[nn][1][0], C[nn][1][1], C[nn][1][2], C[nn][1][3],
                         a10, a11, a12, a13, b0, b1);
            }
        }
        __syncthreads();
    }

    // q prescale: 1/sqrt(D) * log2(e)
    const float QS = 0.17677669529663687f * 1.4426950408889634f;

#pragma unroll
    for (int blk = 0; blk < 2; blk++) {
#pragma unroll
        for (int half = 0; half < 2; half++) {
            int n = n0 + 32 * wid + 16 * blk + 8 * half + g;
            if (n >= NTOK) continue;
            int b = n / SEQ;
            int l = n % SEQ;
#pragma unroll
            for (int nn = 0; nn < 8; nn++) {
                int f = f0 + 8 * nn + 2 * t;
                float v0 = C[nn][blk][2 * half]     + bias[f];
                float v1 = C[nn][blk][2 * half + 1] + bias[f + 1];
                int which = f >> 8;
                int e = f & 255;
                int h = e >> 5;
                int d = e & 31;                    // even
                int bh = b * NHEAD + h;
                if (which == 0) {
                    g_qh[((size_t)bh * SEQ + l) * 16 + (d >> 1)] = h2pack(v0 * QS, v1 * QS);
                } else if (which == 1) {
                    g_kh[((size_t)bh * SEQ + l) * 16 + (d >> 1)] = h2pack(v0, v1);
                } else {
                    g_vt[((size_t)bh * HDIM + d)     * SEQP + l] = __float2half(v0);
                    g_vt[((size_t)bh * HDIM + d + 1) * SEQP + l] = __float2half(v1);
                }
            }
        }
    }
}

// ===========================================================================
// Kernel 2: flash attention, fp16 m16n8k16. BM=128 (8 warps), KV tile 64.
// K smem: [64 rows][20-word pitch] (conflict-free). Vt smem: [32][32] XOR-swz.
// P (C-frag of QK) packs directly into A-frag of PV -> zero shuffles.
// ===========================================================================
__global__ __launch_bounds__(256) void attn_f16_kernel()
{
    const int bh  = blockIdx.y;
    const int l0  = blockIdx.x * 128;
    const int tid = threadIdx.x;
    const int wid = tid >> 5;
    const int lane = tid & 31;
    const int g = lane >> 2;
    const int t = lane & 3;
    const int r_lo = l0 + wid * 16 + g;
    const int r_hi = r_lo + 8;

    __shared__ __align__(16) uint32_t Ks[64 * 20];
    __shared__ __align__(16) uint32_t Vts[32 * 32];

    const uint32_t ks_base = (uint32_t)__cvta_generic_to_shared(Ks);
    const uint32_t vt_base = (uint32_t)__cvta_generic_to_shared(Vts);

    // Q fragments (fp16, prescaled at QKV epilogue)
    const uint32_t* qw = g_qh + (size_t)bh * SEQ * 16;
    uint32_t Aq[2][4];
#pragma unroll
    for (int s = 0; s < 2; s++) {
        Aq[s][0] = Aq[s][1] = Aq[s][2] = Aq[s][3] = 0;
        if (r_lo < SEQ) {
            Aq[s][0] = qw[(size_t)r_lo * 16 + t + 8 * s];
            Aq[s][2] = qw[(size_t)r_lo * 16 + t + 4 + 8 * s];
        }
        if (r_hi < SEQ) {
            Aq[s][1] = qw[(size_t)r_hi * 16 + t + 8 * s];
            Aq[s][3] = qw[(size_t)r_hi * 16 + t + 4 + 8 * s];
        }
    }

    float o[4][4];
#pragma unroll
    for (int nn = 0; nn < 4; nn++)
#pragma unroll
        for (int e = 0; e < 4; e++) o[nn][e] = 0.f;

    float m_lo = -INFINITY, m_hi = -INFINITY;
    float l_lo = 0.f, l_hi = 0.f;

    const int glo = (r_lo < PADSZ) ? (r_lo / GROUPSZ) : -1;
    const int ghi = (r_hi < PADSZ) ? (r_hi / GROUPSZ) : -1;
    const bool blk_has_pad = (l0 < PADSZ);
    const int gminb = l0 / GROUPSZ;
    const int gmaxb = (min(l0 + 127, PADSZ - 1)) / GROUPSZ;

    // staging indices
    const int k_row = tid >> 2;          // 0..63
    const int k_ch  = tid & 3;           // 0..3
    const int v_d   = tid >> 3;          // 0..31
    const int v_ch  = tid & 7;           // 0..7
    const uint32_t k_dst = ks_base + (k_row * 20 + k_ch * 4) * 4;
    const uint32_t v_dst = vt_base + (v_d * 32 + ((v_ch * 4) ^ ((v_d & 7) << 2))) * 4;
    const uint32_t* kbh = g_kh + (size_t)bh * SEQ * 16;
    const __half*   vbh = g_vt + (size_t)bh * HDIM * SEQP;

    for (int m0 = 0; m0 < SEQ; m0 += 64) {
        bool needed = (m0 + 64 > PADSZ);
        if (!needed && blk_has_pad) {
            int gt0 = m0 / GROUPSZ, gt1 = (m0 + 63) / GROUPSZ;
            needed = !(gmaxb < gt0 || gminb > gt1);
        }
        if (!needed) continue;

        __syncthreads();
        {
            int m = m0 + k_row;
            cp_async16(k_dst, kbh + (size_t)(m < SEQ ? m : 0) * 16 + k_ch * 4,
                       (m < SEQ) ? 16u : 0u);
            int ms = m0 + v_ch * 8;
            uint32_t nb = 0;
            if (ms < SEQ) { int rem = (SEQ - ms) * 2; nb = rem >= 16 ? 16u : (uint32_t)rem; }
            cp_async16(v_dst, vbh + (size_t)v_d * SEQP + ms, nb);
            cp_commit();
            cp_wait<0>();
        }
        __syncthreads();

        // --- scores S = Q @ K^T : 16 MMAs ---
        float S[8][4];
#pragma unroll
        for (int j = 0; j < 8; j++) {
            S[j][0] = 0.f; S[j][1] = 0.f; S[j][2] = 0.f; S[j][3] = 0.f;
            int kb = (8 * j + g) * 20;
#pragma unroll
            for (int s = 0; s < 2; s++) {
                uint32_t b0 = Ks[kb + t + 8 * s];
                uint32_t b1 = Ks[kb + t + 4 + 8 * s];
                mma_f16(S[j][0], S[j][1], S[j][2], S[j][3],
                        Aq[s][0], Aq[s][1], Aq[s][2], Aq[s][3], b0, b1);
            }
        }

        // --- mask + rowmax ---
        float tmax_lo = -INFINITY, tmax_hi = -INFINITY;
#pragma unroll
        for (int j = 0; j < 8; j++) {
            int c0 = m0 + 8 * j + 2 * t;
            int c1 = c0 + 1;
            int mg0 = c0 / GROUPSZ;
            int mg1 = c1 / GROUPSZ;
            bool b0lo = (c0 >= SEQ) || (c0 < PADSZ && mg0 != glo);
            bool b1lo = (c1 >= SEQ) || (c1 < PADSZ && mg1 != glo);
            bool b0hi = (c0 >= SEQ) || (c0 < PADSZ && mg0 != ghi);
            bool b1hi = (c1 >= SEQ) || (c1 < PADSZ && mg1 != ghi);
            if (b0lo) S[j][0] = -INFINITY;
            if (b1lo) S[j][1] = -INFINITY;
            if (b0hi) S[j][2] = -INFINITY;
            if (b1hi) S[j][3] = -INFINITY;
            tmax_lo = fmaxf(tmax_lo, fmaxf(S[j][0], S[j][1]));
            tmax_hi = fmaxf(tmax_hi, fmaxf(S[j][2], S[j][3]));
        }
        tmax_lo = fmaxf(tmax_lo, __shfl_xor_sync(0xffffffffu, tmax_lo, 1));
        tmax_lo = fmaxf(tmax_lo, __shfl_xor_sync(0xffffffffu, tmax_lo, 2));
        tmax_hi = fmaxf(tmax_hi, __shfl_xor_sync(0xffffffffu, tmax_hi, 1));
        tmax_hi = fmaxf(tmax_hi, __shfl_xor_sync(0xffffffffu, tmax_hi, 2));

        float mnew_lo = fmaxf(m_lo, tmax_lo);
        float mnew_hi = fmaxf(m_hi, tmax_hi);
        float msafe_lo = (mnew_lo == -INFINITY) ? 0.f : mnew_lo;
        float msafe_hi = (mnew_hi == -INFINITY) ? 0.f : mnew_hi;
        float corr_lo = fast_exp2(m_lo - msafe_lo);
        float corr_hi = fast_exp2(m_hi - msafe_hi);
        m_lo = mnew_lo; m_hi = mnew_hi;

        l_lo *= corr_lo;
        l_hi *= corr_hi;
#pragma unroll
        for (int nn = 0; nn < 4; nn++) {
            o[nn][0] *= corr_lo; o[nn][1] *= corr_lo;
            o[nn][2] *= corr_hi; o[nn][3] *= corr_hi;
        }

#pragma unroll
        for (int j = 0; j < 8; j++) {
            S[j][0] = fast_exp2(S[j][0] - msafe_lo);
            S[j][1] = fast_exp2(S[j][1] - msafe_lo);
            S[j][2] = fast_exp2(S[j][2] - msafe_hi);
            S[j][3] = fast_exp2(S[j][3] - msafe_hi);
            l_lo += S[j][0] + S[j][1];
            l_hi += S[j][2] + S[j][3];
        }

        // --- PV: P C-frag packs directly into fp16 A-frag, 16 MMAs ---
#pragma unroll
        for (int c = 0; c < 4; c++) {
            uint32_t pa0 = h2pack(S[2 * c][0],     S[2 * c][1]);
            uint32_t pa1 = h2pack(S[2 * c][2],     S[2 * c][3]);
            uint32_t pa2 = h2pack(S[2 * c + 1][0], S[2 * c + 1][1]);
            uint32_t pa3 = h2pack(S[2 * c + 1][2], S[2 * c + 1][3]);
#pragma unroll
            for (int nn = 0; nn < 4; nn++) {
                int vr = (8 * nn + g) * 32;
                uint32_t b0 = Vts[vr + ((8 * c + t)     ^ (g << 2))];
                uint32_t b1 = Vts[vr + ((8 * c + t + 4) ^ (g << 2))];
                mma_f16(o[nn][0], o[nn][1], o[nn][2], o[nn][3],
                        pa0, pa1, pa2, pa3, b0, b1);
            }
        }
    }

    l_lo += __shfl_xor_sync(0xffffffffu, l_lo, 1);
    l_lo += __shfl_xor_sync(0xffffffffu, l_lo, 2);
    l_hi += __shfl_xor_sync(0xffffffffu, l_hi, 1);
    l_hi += __shfl_xor_sync(0xffffffffu, l_hi, 2);
    float inv_lo = 1.0f / l_lo;
    float inv_hi = 1.0f / l_hi;

    const int b = bh >> 3;
    const int h = bh & 7;
    if (r_lo < SEQ) {
        float* dst = &g_ctx[((size_t)b * SEQ + r_lo) * EMB + h * HDIM];
#pragma unroll
        for (int nn = 0; nn < 4; nn++)
            *(float2*)&dst[8 * nn + 2 * t] = make_float2(o[nn][0] * inv_lo, o[nn][1] * inv_lo);
    }
    if (r_hi < SEQ) {
        float* dst = &g_ctx[((size_t)b * SEQ + r_hi) * EMB + h * HDIM];
#pragma unroll
        for (int nn = 0; nn < 4; nn++)
            *(float2*)&dst[8 * nn + 2 * t] = make_float2(o[nn][2] * inv_hi, o[nn][3] * inv_hi);
    }
}

// ===========================================================================
// Kernel 3: fused  out = LN(x + ctx @ out_w^T + out_b) * gamma + beta
// BM=64, BN=256 (full row), BK=16, 256 threads (8 warps: 4 row-bands x 2 halves)
// ===========================================================================
__global__ __launch_bounds__(256) void out_ln_kernel(
    const float* __restrict__ x,
    const float* __restrict__ W,      // [256,256]
    const float* __restrict__ bias,
    const float* __restrict__ gamma,
    const float* __restrict__ beta,
    float* __restrict__ out)
{
    __shared__ __align__(16) uint32_t As[2 * 64 * 16];
    __shared__ __align__(16) uint32_t Bs[2 * 256 * 16];
    __shared__ float s_sum[64][2];
    __shared__ float s_sqs[64][2];

    const int n0 = blockIdx.x * 64;
    const int tid = threadIdx.x;
    const int wid = tid >> 5;
    const int lane = tid & 31;
    const int g = lane >> 2;
    const int t = lane & 3;
    const int band = wid & 3;
    const int half = wid >> 2;

    float C[16][4];
#pragma unroll
    for (int nn = 0; nn < 16; nn++)
#pragma unroll
        for (int e = 0; e < 4; e++) C[nn][e] = 0.f;

    const uint32_t as_base = (uint32_t)__cvta_generic_to_shared(As);
    const uint32_t bs_base = (uint32_t)__cvta_generic_to_shared(Bs);
    // swizzle: word w of row r stored at w ^ ((((r)&7)>>1)<<2)
    auto swz = [](int r) { return ((r & 7) >> 1) << 2; };

    auto load_stage = [&](int kc, int stage) {
        int k0 = kc * 16;
        uint32_t a_st = as_base + stage * (64 * 16 * 4);
        uint32_t b_st = bs_base + stage * (256 * 16 * 4);
        // A: 64 rows x 4 chunks = 256 tasks (1/thread)
        {
            int row = tid >> 2;
            int c4  = (tid & 3) * 4;
            int off = row * 16 + (c4 ^ swz(row));
            int gn = n0 + row;
            bool ok = (gn < NTOK);
            const float* src = g_ctx + (size_t)(ok ? gn : 0) * 256 + k0 + c4;
            cp_async16(a_st + off * 4, src, ok ? 16u : 0u);
        }
        // B: 256 rows x 4 chunks = 1024 tasks (4/thread)
#pragma unroll
        for (int i = 0; i < 4; i++) {
            int idx = tid + i * 256;
            int row = idx >> 2;
            int c4  = (idx & 3) * 4;
            int off = row * 16 + (c4 ^ swz(row));
            const float* src = W + (size_t)row * 256 + k0 + c4;
            cp_async16(b_st + off * 4, src, 16u);
        }
        cp_commit();
    };

    load_stage(0, 0);

    const int R0 = 16 * band + g;
    const int sA = swz(g);

    for (int kc = 0; kc < 16; kc++) {
        int buf = kc & 1;
        if (kc + 1 < 16) { load_stage(kc + 1, buf ^ 1); cp_wait<1>(); }
        else            { cp_wait<0>(); }
        __syncthreads();

        const uint32_t* as = As + buf * (64 * 16);
        const uint32_t* bs = Bs + buf * (256 * 16);

#pragma unroll
        for (int s = 0; s < 2; s++) {
            int kl = 8 * s + t;
            int kh = kl + 4;
            uint32_t a0 = as[R0 * 16       + (kl ^ sA)];
            uint32_t a1 = as[(R0 + 8) * 16 + (kl ^ sA)];
            uint32_t a2 = as[R0 * 16       + (kh ^ sA)];
            uint32_t a3 = as[(R0 + 8) * 16 + (kh ^ sA)];
#pragma unroll
            for (int nn = 0; nn < 16; nn++) {
                int fr = 128 * half + 8 * nn + g;
                uint32_t b0 = bs[fr * 16 + (kl ^ sA)];
                uint32_t b1 = bs[fr * 16 + (kh ^ sA)];
                mma_tf32(C[nn][0], C[nn][1], C[nn][2], C[nn][3],
                         a0, a1, a2, a3, b0, b1);
            }
        }
        __syncthreads();
    }

    // epilogue: bias + residual, LN stats, normalize, write
    const int r0 = n0 + 16 * band + g;
    const int r1 = r0 + 8;
    float sum_lo = 0.f, sqs_lo = 0.f, sum_hi = 0.f, sqs_hi = 0.f;
#pragma unroll
    for (int nn = 0; nn < 16; nn++) {
        int f = 128 * half + 8 * nn + 2 * t;
        float b0 = bias[f], b1 = bias[f + 1];
        if (r0 < NTOK) {
            float2 xr = *(const float2*)&x[(size_t)r0 * 256 + f];
            C[nn][0] += b0 + xr.x;
            C[nn][1] += b1 + xr.y;
        }
        if (r1 < NTOK) {
            float2 xr = *(const float2*)&x[(size_t)r1 * 256 + f];
            C[nn][2] += b0 + xr.x;
            C[nn][3] += b1 + xr.y;
        }
        sum_lo += C[nn][0] + C[nn][1];
        sqs_lo += C[nn][0] * C[nn][0] + C[nn][1] * C[nn][1];
        sum_hi += C[nn][2] + C[nn][3];
        sqs_hi += C[nn][2] * C[nn][2] + C[nn][3] * C[nn][3];
    }
    // quad reduce over t
    sum_lo += __shfl_xor_sync(0xffffffffu, sum_lo, 1);
    sum_lo += __shfl_xor_sync(0xffffffffu, sum_lo, 2);
    sqs_lo += __shfl_xor_sync(0xffffffffu, sqs_lo, 1);
    sqs_lo += __shfl_xor_sync(0xffffffffu, sqs_lo, 2);
    sum_hi += __shfl_xor_sync(0xffffffffu, sum_hi, 1);
    sum_hi += __shfl_xor_sync(0xffffffffu, sum_hi, 2);
    sqs_hi += __shfl_xor_sync(0xffffffffu, sqs_hi, 1);
    sqs_hi += __shfl_xor_sync(0xffffffffu, sqs_hi, 2);

    if (t == 0) {
        s_sum[16 * band + g][half] = sum_lo;
        s_sqs[16 * band + g][half] = sqs_lo;
        s_sum[16 * band + g + 8][half] = sum_hi;
        s_sqs[16 * band + g + 8][half] = sqs_hi;
    }
    __syncthreads();

    float S1lo = s_sum[16 * band + g][0] + s_sum[16 * band + g][1];
    float S2lo = s_sqs[16 * band + g][0] + s_sqs[16 * band + g][1];
    float S1hi = s_sum[16 * band + g + 8][0] + s_sum[16 * band + g + 8][1];
    float S2hi = s_sqs[16 * band + g + 8][0] + s_sqs[16 * band + g + 8][1];

    float mean_lo = S1lo * (1.0f / 256.0f);
    float var_lo  = S2lo * (1.0f / 256.0f) - mean_lo * mean_lo;
    float rs_lo   = rsqrtf(var_lo + LNEPS);
    float mean_hi = S1hi * (1.0f / 256.0f);
    float var_hi  = S2hi * (1.0f / 256.0f) - mean_hi * mean_hi;
    float rs_hi   = rsqrtf(var_hi + LNEPS);

#pragma unroll
    for (int nn = 0; nn < 16; nn++) {
        int f = 128 * half + 8 * nn + 2 * t;
        float gm0 = gamma[f], gm1 = gamma[f + 1];
        float bt0 = beta[f],  bt1 = beta[f + 1];
        if (r0 < NTOK) {
            float2 w;
            w.x = (C[nn][0] - mean_lo) * rs_lo * gm0 + bt0;
            w.y = (C[nn][1] - mean_lo) * rs_lo * gm1 + bt1;
            *(float2*)&out[(size_t)r0 * 256 + f] = w;
        }
        if (r1 < NTOK) {
            float2 w;
            w.x = (C[nn][2] - mean_hi) * rs_hi * gm0 + bt0;
            w.y = (C[nn][3] - mean_hi) * rs_hi * gm1 + bt1;
            *(float2*)&out[(size_t)r1 * 256 + f] = w;
        }
    }
}

// ---------------------------------------------------------------------------
extern "C" void kernel_launch(void* const* d_in, const int* in_sizes, int n_in,
                              void* d_out, int out_size)
{
    const float* x     = (const float*)d_in[0];
    const float* in_w  = (const float*)d_in[1];
    const float* in_b  = (const float*)d_in[2];
    const float* out_w = (const float*)d_in[3];
    const float* out_b = (const float*)d_in[4];
    const float* ln_g  = (const float*)d_in[5];
    const float* ln_b  = (const float*)d_in[6];
    float* out = (float*)d_out;

    qkv_mma_kernel<<<dim3((NTOK + 127) / 128, F3 / 64), 128>>>(x, in_w, in_b);
    attn_f16_kernel<<<dim3((SEQ + 127) / 128, BATCH * NHEAD), 256>>>();
    out_ln_kernel<<<(NTOK + 63) / 64, 256>>>(x, out_w, out_b, ln_g, ln_b, out);
}

// round 10
// speedup vs baseline: 4.7519x; 1.0303x over previous
#include <cuda_runtime.h>
#include <cuda_fp16.h>
#include <math.h>
#include <stdint.h>

#define BATCH 8
#define SEQ 1900
#define SEQP 1904
#define EMB 256
#define NHEAD 8
#define HDIM 32
#define NTOK (BATCH*SEQ)       // 15200
#define F3 (3*EMB)             // 768
#define PADSZ 1000
#define GROUPSZ 200
#define LNEPS 1e-5f
#define QP 20                  // smem pitch in u32 words (conflict-free: 20g mod 32 distinct)

// ---------------- scratch (device globals, no allocations) ----------------
__device__ __align__(16) uint32_t g_xh [NTOK*128];            // x fp16, [n][128 words]
__device__ __align__(16) uint32_t g_wih[F3*128];              // in_w fp16
__device__ __align__(16) uint32_t g_woh[EMB*128];             // out_w fp16
__device__ __align__(16) uint32_t g_qh [BATCH*NHEAD*SEQ*16];  // q fp16 prescaled
__device__ __align__(16) uint32_t g_kh [BATCH*NHEAD*SEQ*16];  // k fp16
__device__ __align__(16) __half   g_vt [BATCH*NHEAD*HDIM*SEQP]; // v fp16 transposed [bh][d][l]
__device__ __align__(16) uint32_t g_ctxh[NTOK*128];           // ctx fp16

__device__ __forceinline__ float fast_exp2(float x) {
    float y;
    asm("ex2.approx.ftz.f32 %0, %1;" : "=f"(y) : "f"(x));
    return y;
}
__device__ __forceinline__ uint32_t h2pack(float a, float b) {
    __half2 h = __floats2half2_rn(a, b);
    return *(uint32_t*)&h;
}
__device__ __forceinline__ void mma_f16(float& c0, float& c1, float& c2, float& c3,
                                        uint32_t a0, uint32_t a1, uint32_t a2, uint32_t a3,
                                        uint32_t b0, uint32_t b1) {
    asm volatile(
        "mma.sync.aligned.m16n8k16.row.col.f32.f16.f16.f32 "
        "{%0,%1,%2,%3}, {%4,%5,%6,%7}, {%8,%9}, {%0,%1,%2,%3};"
        : "+f"(c0), "+f"(c1), "+f"(c2), "+f"(c3)
        : "r"(a0), "r"(a1), "r"(a2), "r"(a3), "r"(b0), "r"(b1));
}
__device__ __forceinline__ void cp_async16(uint32_t smem_addr, const void* gsrc, uint32_t src_bytes) {
    asm volatile("cp.async.cg.shared.global [%0], [%1], 16, %2;\n"
                 :: "r"(smem_addr), "l"(gsrc), "r"(src_bytes));
}
__device__ __forceinline__ void cp_commit() {
    asm volatile("cp.async.commit_group;\n");
}
template <int N>
__device__ __forceinline__ void cp_wait() {
    asm volatile("cp.async.wait_group %0;\n" :: "n"(N));
}

// ===========================================================================
// Kernel 0: fp32 -> fp16 conversion of x, in_w, out_w
// ===========================================================================
#define NX4  (NTOK*64)
#define NWI4 (F3*64)
#define NWO4 (EMB*64)
__global__ __launch_bounds__(256) void cvt_kernel(
    const float* __restrict__ x,
    const float* __restrict__ wi,
    const float* __restrict__ wo)
{
    int i = blockIdx.x * blockDim.x + threadIdx.x;
    float4 v;
    uint2* dst;
    if (i < NX4)                 { v = ((const float4*)x)[i];  dst = (uint2*)g_xh + i; }
    else if (i < NX4 + NWI4)     { int j = i - NX4;  v = ((const float4*)wi)[j]; dst = (uint2*)g_wih + j; }
    else if (i < NX4 + NWI4 + NWO4) { int j = i - NX4 - NWI4; v = ((const float4*)wo)[j]; dst = (uint2*)g_woh + j; }
    else return;
    uint2 r;
    r.x = h2pack(v.x, v.y);
    r.y = h2pack(v.z, v.w);
    *dst = r;
}

// ===========================================================================
// Kernel 1: QKV = x @ W^T + b  (fp16 MMA, BM=128 BN=64 BK=32, 3-stage cp.async)
// Epilogue: q fp16 prescaled, k fp16, v fp16 transposed
// ===========================================================================
__global__ __launch_bounds__(128) void qkv_h_kernel(const float* __restrict__ bias)
{
    __shared__ __align__(16) uint32_t As[3 * 128 * QP];
    __shared__ __align__(16) uint32_t Bs[3 * 64 * QP];

    const int n0 = blockIdx.x * 128;
    const int f0 = blockIdx.y * 64;
    const int tid = threadIdx.x;
    const int wid = tid >> 5;
    const int lane = tid & 31;
    const int g = lane >> 2;
    const int t = lane & 3;
    const int rw = 32 * wid;

    float C[8][2][4];
#pragma unroll
    for (int nn = 0; nn < 8; nn++)
#pragma unroll
        for (int b = 0; b < 2; b++)
#pragma unroll
            for (int e = 0; e < 4; e++) C[nn][b][e] = 0.f;

    const uint32_t as_base = (uint32_t)__cvta_generic_to_shared(As);
    const uint32_t bs_base = (uint32_t)__cvta_generic_to_shared(Bs);

    auto load_stage = [&](int kc, int st) {
        int k0 = kc * 16;   // word offset within the 128-word row
        uint32_t a_st = as_base + st * (128 * QP) * 4;
        uint32_t b_st = bs_base + st * (64 * QP) * 4;
#pragma unroll
        for (int i = 0; i < 4; i++) {
            int idx = tid + i * 128;
            int row = idx >> 2;
            int ch  = idx & 3;
            int gn = n0 + row;
            bool ok = (gn < NTOK);
            cp_async16(a_st + (row * QP + ch * 4) * 4,
                       g_xh + (size_t)(ok ? gn : 0) * 128 + k0 + ch * 4, ok ? 16u : 0u);
        }
#pragma unroll
        for (int i = 0; i < 2; i++) {
            int idx = tid + i * 128;
            int row = idx >> 2;
            int ch  = idx & 3;
            cp_async16(b_st + (row * QP + ch * 4) * 4,
                       g_wih + (size_t)(f0 + row) * 128 + k0 + ch * 4, 16u);
        }
        cp_commit();
    };

    load_stage(0, 0);
    load_stage(1, 1);

    for (int kc = 0; kc < 8; kc++) {
        __syncthreads();
        if (kc + 2 < 8) { load_stage(kc + 2, (kc + 2) % 3); cp_wait<2>(); }
        else if (kc + 1 < 8) { cp_wait<1>(); }
        else { cp_wait<0>(); }
        __syncthreads();

        const uint32_t* as = As + (kc % 3) * (128 * QP);
        const uint32_t* bs = Bs + (kc % 3) * (64 * QP);

#pragma unroll
        for (int s = 0; s < 2; s++) {
            int wl = 8 * s + t;
            int wh = wl + 4;
            uint32_t a00 = as[(rw + g)      * QP + wl];
            uint32_t a01 = as[(rw + g + 8)  * QP + wl];
            uint32_t a02 = as[(rw + g)      * QP + wh];
            uint32_t a03 = as[(rw + g + 8)  * QP + wh];
            uint32_t a10 = as[(rw + g + 16) * QP + wl];
            uint32_t a11 = as[(rw + g + 24) * QP + wl];
            uint32_t a12 = as[(rw + g + 16) * QP + wh];
            uint32_t a13 = as[(rw + g + 24) * QP + wh];
#pragma unroll
            for (int nn = 0; nn < 8; nn++) {
                int fr = 8 * nn + g;
                uint32_t b0 = bs[fr * QP + wl];
                uint32_t b1 = bs[fr * QP + wh];
                mma_f16(C[nn][0][0], C[nn][0][1], C[nn][0][2], C[nn][0][3],
                        a00, a01, a02, a03, b0, b1);
                mma_f16(C[nn][1][0], C[nn][1][1], C[nn][1][2], C[nn][1][3],
                        a10, a11, a12, a13, b0, b1);
            }
        }
    }

    const float QS = 0.17677669529663687f * 1.4426950408889634f;

#pragma unroll
    for (int blk = 0; blk < 2; blk++) {
#pragma unroll
        for (int half = 0; half < 2; half++) {
            int n = n0 + 32 * wid + 16 * blk + 8 * half + g;
            if (n >= NTOK) continue;
            int b = n / SEQ;
            int l = n % SEQ;
#pragma unroll
            for (int nn = 0; nn < 8; nn++) {
                int f = f0 + 8 * nn + 2 * t;
                float v0 = C[nn][blk][2 * half]     + bias[f];
                float v1 = C[nn][blk][2 * half + 1] + bias[f + 1];
                int which = f >> 8;
                int e = f & 255;
                int h = e >> 5;
                int d = e & 31;
                int bh = b * NHEAD + h;
                if (which == 0) {
                    g_qh[((size_t)bh * SEQ + l) * 16 + (d >> 1)] = h2pack(v0 * QS, v1 * QS);
                } else if (which == 1) {
                    g_kh[((size_t)bh * SEQ + l) * 16 + (d >> 1)] = h2pack(v0, v1);
                } else {
                    g_vt[((size_t)bh * HDIM + d)     * SEQP + l] = __float2half(v0);
                    g_vt[((size_t)bh * HDIM + d + 1) * SEQP + l] = __float2half(v1);
                }
            }
        }
    }
}

// ===========================================================================
// Kernel 2: flash attention fp16, double-buffered KV staging, ctx out fp16
// ===========================================================================
__global__ __launch_bounds__(256) void attn_f16_kernel()
{
    const int bh  = blockIdx.y;
    const int l0  = blockIdx.x * 128;
    const int tid = threadIdx.x;
    const int wid = tid >> 5;
    const int lane = tid & 31;
    const int g = lane >> 2;
    const int t = lane & 3;
    const int r_lo = l0 + wid * 16 + g;
    const int r_hi = r_lo + 8;

    __shared__ __align__(16) uint32_t Ks[2 * 64 * 20];
    __shared__ __align__(16) uint32_t Vts[2 * 32 * 32];

    const uint32_t ks_base = (uint32_t)__cvta_generic_to_shared(Ks);
    const uint32_t vt_base = (uint32_t)__cvta_generic_to_shared(Vts);

    const uint32_t* qw = g_qh + (size_t)bh * SEQ * 16;
    uint32_t Aq[2][4];
#pragma unroll
    for (int s = 0; s < 2; s++) {
        Aq[s][0] = Aq[s][1] = Aq[s][2] = Aq[s][3] = 0;
        if (r_lo < SEQ) {
            Aq[s][0] = qw[(size_t)r_lo * 16 + t + 8 * s];
            Aq[s][2] = qw[(size_t)r_lo * 16 + t + 4 + 8 * s];
        }
        if (r_hi < SEQ) {
            Aq[s][1] = qw[(size_t)r_hi * 16 + t + 8 * s];
            Aq[s][3] = qw[(size_t)r_hi * 16 + t + 4 + 8 * s];
        }
    }

    float o[4][4];
#pragma unroll
    for (int nn = 0; nn < 4; nn++)
#pragma unroll
        for (int e = 0; e < 4; e++) o[nn][e] = 0.f;

    float m_lo = -INFINITY, m_hi = -INFINITY;
    float l_lo = 0.f, l_hi = 0.f;

    const int glo = (r_lo < PADSZ) ? (r_lo / GROUPSZ) : -1;
    const int ghi = (r_hi < PADSZ) ? (r_hi / GROUPSZ) : -1;
    const bool blk_has_pad = (l0 < PADSZ);
    const int gminb = l0 / GROUPSZ;
    const int gmaxb = (min(l0 + 127, PADSZ - 1)) / GROUPSZ;

    auto tile_needed = [&](int m0) -> bool {
        if (m0 + 64 > PADSZ) return true;
        if (!blk_has_pad) return false;
        int gt0 = m0 / GROUPSZ, gt1 = (m0 + 63) / GROUPSZ;
        return !(gmaxb < gt0 || gminb > gt1);
    };

    const int k_row = tid >> 2;
    const int k_ch  = tid & 3;
    const int v_d   = tid >> 3;
    const int v_ch  = tid & 7;
    const uint32_t* kbh = g_kh + (size_t)bh * SEQ * 16;
    const __half*   vbh = g_vt + (size_t)bh * HDIM * SEQP;

    auto load_tile = [&](int m0, int buf) {
        uint32_t k_dst = ks_base + (buf * (64 * 20) + k_row * 20 + k_ch * 4) * 4;
        uint32_t v_dst = vt_base + (buf * (32 * 32) + v_d * 32 + ((v_ch * 4) ^ ((v_d & 7) << 2))) * 4;
        int m = m0 + k_row;
        cp_async16(k_dst, kbh + (size_t)(m < SEQ ? m : 0) * 16 + k_ch * 4,
                   (m < SEQ) ? 16u : 0u);
        int ms = m0 + v_ch * 8;
        uint32_t nb = 0;
        if (ms < SEQ) { int rem = (SEQ - ms) * 2; nb = rem >= 16 ? 16u : (uint32_t)rem; }
        cp_async16(v_dst, vbh + (size_t)v_d * SEQP + ms, nb);
        cp_commit();
    };

    int m0 = 0;
    while (m0 < SEQ && !tile_needed(m0)) m0 += 64;
    if (m0 < SEQ) load_tile(m0, 0);
    int buf = 0;

    while (m0 < SEQ) {
        int mn = m0 + 64;
        while (mn < SEQ && !tile_needed(mn)) mn += 64;

        __syncthreads();
        if (mn < SEQ) { load_tile(mn, buf ^ 1); cp_wait<1>(); }
        else          { cp_wait<0>(); }
        __syncthreads();

        const uint32_t* ks = Ks + buf * (64 * 20);
        const uint32_t* vs = Vts + buf * (32 * 32);

        float S[8][4];
#pragma unroll
        for (int j = 0; j < 8; j++) {
            S[j][0] = 0.f; S[j][1] = 0.f; S[j][2] = 0.f; S[j][3] = 0.f;
            int kb = (8 * j + g) * 20;
#pragma unroll
            for (int s = 0; s < 2; s++) {
                uint32_t b0 = ks[kb + t + 8 * s];
                uint32_t b1 = ks[kb + t + 4 + 8 * s];
                mma_f16(S[j][0], S[j][1], S[j][2], S[j][3],
                        Aq[s][0], Aq[s][1], Aq[s][2], Aq[s][3], b0, b1);
            }
        }

        float tmax_lo = -INFINITY, tmax_hi = -INFINITY;
#pragma unroll
        for (int j = 0; j < 8; j++) {
            int c0 = m0 + 8 * j + 2 * t;
            int c1 = c0 + 1;
            int mg0 = c0 / GROUPSZ;
            int mg1 = c1 / GROUPSZ;
            bool b0lo = (c0 >= SEQ) || (c0 < PADSZ && mg0 != glo);
            bool b1lo = (c1 >= SEQ) || (c1 < PADSZ && mg1 != glo);
            bool b0hi = (c0 >= SEQ) || (c0 < PADSZ && mg0 != ghi);
            bool b1hi = (c1 >= SEQ) || (c1 < PADSZ && mg1 != ghi);
            if (b0lo) S[j][0] = -INFINITY;
            if (b1lo) S[j][1] = -INFINITY;
            if (b0hi) S[j][2] = -INFINITY;
            if (b1hi) S[j][3] = -INFINITY;
            tmax_lo = fmaxf(tmax_lo, fmaxf(S[j][0], S[j][1]));
            tmax_hi = fmaxf(tmax_hi, fmaxf(S[j][2], S[j][3]));
        }
        tmax_lo = fmaxf(tmax_lo, __shfl_xor_sync(0xffffffffu, tmax_lo, 1));
        tmax_lo = fmaxf(tmax_lo, __shfl_xor_sync(0xffffffffu, tmax_lo, 2));
        tmax_hi = fmaxf(tmax_hi, __shfl_xor_sync(0xffffffffu, tmax_hi, 1));
        tmax_hi = fmaxf(tmax_hi, __shfl_xor_sync(0xffffffffu, tmax_hi, 2));

        float mnew_lo = fmaxf(m_lo, tmax_lo);
        float mnew_hi = fmaxf(m_hi, tmax_hi);
        float msafe_lo = (mnew_lo == -INFINITY) ? 0.f : mnew_lo;
        float msafe_hi = (mnew_hi == -INFINITY) ? 0.f : mnew_hi;
        float corr_lo = fast_exp2(m_lo - msafe_lo);
        float corr_hi = fast_exp2(m_hi - msafe_hi);
        m_lo = mnew_lo; m_hi = mnew_hi;

        l_lo *= corr_lo;
        l_hi *= corr_hi;
#pragma unroll
        for (int nn = 0; nn < 4; nn++) {
            o[nn][0] *= corr_lo; o[nn][1] *= corr_lo;
            o[nn][2] *= corr_hi; o[nn][3] *= corr_hi;
        }

#pragma unroll
        for (int j = 0; j < 8; j++) {
            S[j][0] = fast_exp2(S[j][0] - msafe_lo);
            S[j][1] = fast_exp2(S[j][1] - msafe_lo);
            S[j][2] = fast_exp2(S[j][2] - msafe_hi);
            S[j][3] = fast_exp2(S[j][3] - msafe_hi);
            l_lo += S[j][0] + S[j][1];
            l_hi += S[j][2] + S[j][3];
        }

#pragma unroll
        for (int c = 0; c < 4; c++) {
            uint32_t pa0 = h2pack(S[2 * c][0],     S[2 * c][1]);
            uint32_t pa1 = h2pack(S[2 * c][2],     S[2 * c][3]);
            uint32_t pa2 = h2pack(S[2 * c + 1][0], S[2 * c + 1][1]);
            uint32_t pa3 = h2pack(S[2 * c + 1][2], S[2 * c + 1][3]);
#pragma unroll
            for (int nn = 0; nn < 4; nn++) {
                int vr = (8 * nn + g) * 32;
                uint32_t b0 = vs[vr + ((8 * c + t)     ^ (g << 2))];
                uint32_t b1 = vs[vr + ((8 * c + t + 4) ^ (g << 2))];
                mma_f16(o[nn][0], o[nn][1], o[nn][2], o[nn][3],
                        pa0, pa1, pa2, pa3, b0, b1);
            }
        }

        buf ^= 1;
        m0 = mn;
    }

    l_lo += __shfl_xor_sync(0xffffffffu, l_lo, 1);
    l_lo += __shfl_xor_sync(0xffffffffu, l_lo, 2);
    l_hi += __shfl_xor_sync(0xffffffffu, l_hi, 1);
    l_hi += __shfl_xor_sync(0xffffffffu, l_hi, 2);
    float inv_lo = 1.0f / l_lo;
    float inv_hi = 1.0f / l_hi;

    const int b = bh >> 3;
    const int h = bh & 7;
    if (r_lo < SEQ) {
        uint32_t* dst = &g_ctxh[((size_t)b * SEQ + r_lo) * 128 + h * 16];
#pragma unroll
        for (int nn = 0; nn < 4; nn++)
            dst[4 * nn + t] = h2pack(o[nn][0] * inv_lo, o[nn][1] * inv_lo);
    }
    if (r_hi < SEQ) {
        uint32_t* dst = &g_ctxh[((size_t)b * SEQ + r_hi) * 128 + h * 16];
#pragma unroll
        for (int nn = 0; nn < 4; nn++)
            dst[4 * nn + t] = h2pack(o[nn][2] * inv_hi, o[nn][3] * inv_hi);
    }
}

// ===========================================================================
// Kernel 3: fused out = LN(x + ctx @ out_w^T + out_b)
// BM=32, BN=256, BK=32 fp16, 256 threads (2 row-bands x 4 col-quarters)
// ===========================================================================
__global__ __launch_bounds__(256) void out_ln_kernel(
    const float* __restrict__ x,
    const float* __restrict__ bias,
    const float* __restrict__ gamma,
    const float* __restrict__ beta,
    float* __restrict__ out)
{
    __shared__ __align__(16) uint32_t As[2 * 32 * QP];
    __shared__ __align__(16) uint32_t Bs[2 * 256 * QP];
    __shared__ float s_sum[32][4];
    __shared__ float s_sqs[32][4];

    const int n0 = blockIdx.x * 32;
    const int tid = threadIdx.x;
    const int wid = tid >> 5;
    const int lane = tid & 31;
    const int g = lane >> 2;
    const int t = lane & 3;
    const int band = wid >> 2;     // 0..1 (16 rows each)
    const int quad = wid & 3;      // 0..3 (64 cols each)

    float C[8][4];
#pragma unroll
    for (int nn = 0; nn < 8; nn++)
#pragma unroll
        for (int e = 0; e < 4; e++) C[nn][e] = 0.f;

    const uint32_t as_base = (uint32_t)__cvta_generic_to_shared(As);
    const uint32_t bs_base = (uint32_t)__cvta_generic_to_shared(Bs);

    auto load_stage = [&](int kc, int st) {
        int k0 = kc * 16;
        uint32_t a_st = as_base + st * (32 * QP) * 4;
        uint32_t b_st = bs_base + st * (256 * QP) * 4;
        if (tid < 128) {           // 32 rows x 4 chunks
            int row = tid >> 2;
            int ch  = tid & 3;
            cp_async16(a_st + (row * QP + ch * 4) * 4,
                       g_ctxh + (size_t)(n0 + row) * 128 + k0 + ch * 4, 16u);
        }
#pragma unroll
        for (int i = 0; i < 4; i++) {
            int idx = tid + i * 256;
            int row = idx >> 2;
            int ch  = idx & 3;
            cp_async16(b_st + (row * QP + ch * 4) * 4,
                       g_woh + (size_t)row * 128 + k0 + ch * 4, 16u);
        }
        cp_commit();
    };

    load_stage(0, 0);

    const int R0 = 16 * band + g;

    for (int kc = 0; kc < 8; kc++) {
        __syncthreads();
        if (kc + 1 < 8) { load_stage(kc + 1, (kc + 1) & 1); cp_wait<1>(); }
        else            { cp_wait<0>(); }
        __syncthreads();

        const uint32_t* as = As + (kc & 1) * (32 * QP);
        const uint32_t* bs = Bs + (kc & 1) * (256 * QP);

#pragma unroll
        for (int s = 0; s < 2; s++) {
            int wl = 8 * s + t;
            int wh = wl + 4;
            uint32_t a0 = as[R0 * QP + wl];
            uint32_t a1 = as[(R0 + 8) * QP + wl];
            uint32_t a2 = as[R0 * QP + wh];
            uint32_t a3 = as[(R0 + 8) * QP + wh];
#pragma unroll
            for (int nn = 0; nn < 8; nn++) {
                int fr = 64 * quad + 8 * nn + g;
                uint32_t b0 = bs[fr * QP + wl];
                uint32_t b1 = bs[fr * QP + wh];
                mma_f16(C[nn][0], C[nn][1], C[nn][2], C[nn][3],
                        a0, a1, a2, a3, b0, b1);
            }
        }
    }

    // epilogue: bias + residual, LN stats, normalize, write (all rows in-bounds)
    const int r0 = n0 + 16 * band + g;
    const int r1 = r0 + 8;
    float sum_lo = 0.f, sqs_lo = 0.f, sum_hi = 0.f, sqs_hi = 0.f;
#pragma unroll
    for (int nn = 0; nn < 8; nn++) {
        int f = 64 * quad + 8 * nn + 2 * t;
        float b0 = bias[f], b1 = bias[f + 1];
        float2 xr0 = *(const float2*)&x[(size_t)r0 * 256 + f];
        float2 xr1 = *(const float2*)&x[(size_t)r1 * 256 + f];
        C[nn][0] += b0 + xr0.x;
        C[nn][1] += b1 + xr0.y;
        C[nn][2] += b0 + xr1.x;
        C[nn][3] += b1 + xr1.y;
        sum_lo += C[nn][0] + C[nn][1];
        sqs_lo += C[nn][0] * C[nn][0] + C[nn][1] * C[nn][1];
        sum_hi += C[nn][2] + C[nn][3];
        sqs_hi += C[nn][2] * C[nn][2] + C[nn][3] * C[nn][3];
    }
    sum_lo += __shfl_xor_sync(0xffffffffu, sum_lo, 1);
    sum_lo += __shfl_xor_sync(0xffffffffu, sum_lo, 2);
    sqs_lo += __shfl_xor_sync(0xffffffffu, sqs_lo, 1);
    sqs_lo += __shfl_xor_sync(0xffffffffu, sqs_lo, 2);
    sum_hi += __shfl_xor_sync(0xffffffffu, sum_hi, 1);
    sum_hi += __shfl_xor_sync(0xffffffffu, sum_hi, 2);
    sqs_hi += __shfl_xor_sync(0xffffffffu, sqs_hi, 1);
    sqs_hi += __shfl_xor_sync(0xffffffffu, sqs_hi, 2);

    if (t == 0) {
        s_sum[16 * band + g][quad] = sum_lo;
        s_sqs[16 * band + g][quad] = sqs_lo;
        s_sum[16 * band + g + 8][quad] = sum_hi;
        s_sqs[16 * band + g + 8][quad] = sqs_hi;
    }
    __syncthreads();

    float S1lo = s_sum[16 * band + g][0] + s_sum[16 * band + g][1]
               + s_sum[16 * band + g][2] + s_sum[16 * band + g][3];
    float S2lo = s_sqs[16 * band + g][0] + s_sqs[16 * band + g][1]
               + s_sqs[16 * band + g][2] + s_sqs[16 * band + g][3];
    float S1hi = s_sum[16 * band + g + 8][0] + s_sum[16 * band + g + 8][1]
               + s_sum[16 * band + g + 8][2] + s_sum[16 * band + g + 8][3];
    float S2hi = s_sqs[16 * band + g + 8][0] + s_sqs[16 * band + g + 8][1]
               + s_sqs[16 * band + g + 8][2] + s_sqs[16 * band + g + 8][3];

    float mean_lo = S1lo * (1.0f / 256.0f);
    float var_lo  = S2lo * (1.0f / 256.0f) - mean_lo * mean_lo;
    float rs_lo   = rsqrtf(var_lo + LNEPS);
    float mean_hi = S1hi * (1.0f / 256.0f);
    float var_hi  = S2hi * (1.0f / 256.0f) - mean_hi * mean_hi;
    float rs_hi   = rsqrtf(var_hi + LNEPS);

#pragma unroll
    for (int nn = 0; nn < 8; nn++) {
        int f = 64 * quad + 8 * nn + 2 * t;
        float gm0 = gamma[f], gm1 = gamma[f + 1];
        float bt0 = beta[f],  bt1 = beta[f + 1];
        float2 w0, w1;
        w0.x = (C[nn][0] - mean_lo) * rs_lo * gm0 + bt0;
        w0.y = (C[nn][1] - mean_lo) * rs_lo * gm1 + bt1;
        w1.x = (C[nn][2] - mean_hi) * rs_hi * gm0 + bt0;
        w1.y = (C[nn][3] - mean_hi) * rs_hi * gm1 + bt1;
        *(float2*)&out[(size_t)r0 * 256 + f] = w0;
        *(float2*)&out[(size_t)r1 * 256 + f] = w1;
    }
}

// ---------------------------------------------------------------------------
extern "C" void kernel_launch(void* const* d_in, const int* in_sizes, int n_in,
                              void* d_out, int out_size)
{
    const float* x     = (const float*)d_in[0];
    const float* in_w  = (const float*)d_in[1];
    const float* in_b  = (const float*)d_in[2];
    const float* out_w = (const float*)d_in[3];
    const float* out_b = (const float*)d_in[4];
    const float* ln_g  = (const float*)d_in[5];
    const float* ln_b  = (const float*)d_in[6];
    float* out = (float*)d_out;

    cvt_kernel<<<(NX4 + NWI4 + NWO4 + 255) / 256, 256>>>(x, in_w, out_w);
    qkv_h_kernel<<<dim3((NTOK + 127) / 128, F3 / 64), 128>>>(in_b);
    attn_f16_kernel<<<dim3((SEQ + 127) / 128, BATCH * NHEAD), 256>>>();
    out_ln_kernel<<<NTOK / 32, 256>>>(x, out_b, ln_g, ln_b, out);
}

// round 11
// speedup vs baseline: 6.1775x; 1.3000x over previous
#include <cuda_runtime.h>
#include <cuda_fp16.h>
#include <math.h>
#include <stdint.h>

#define BATCH 8
#define SEQ 1900
#define SEQP 1904
#define EMB 256
#define NHEAD 8
#define HDIM 32
#define NTOK (BATCH*SEQ)       // 15200
#define F3 (3*EMB)             // 768
#define PADSZ 1000
#define GROUPSZ 200
#define LNEPS 1e-5f
#define QP 20                  // smem pitch (u32 words) for qkv kernel

// ---------------- scratch (device globals, no allocations) ----------------
__device__ __align__(16) uint32_t g_xh [NTOK*128];
__device__ __align__(16) uint32_t g_wih[F3*128];
__device__ __align__(16) uint32_t g_woh[EMB*128];
__device__ __align__(16) uint32_t g_qh [BATCH*NHEAD*SEQ*16];
__device__ __align__(16) uint32_t g_kh [BATCH*NHEAD*SEQ*16];
__device__ __align__(16) __half   g_vt [BATCH*NHEAD*HDIM*SEQP];
__device__ __align__(16) uint32_t g_ctxh[NTOK*128];

__device__ __forceinline__ float fast_exp2(float x) {
    float y;
    asm("ex2.approx.ftz.f32 %0, %1;" : "=f"(y) : "f"(x));
    return y;
}
__device__ __forceinline__ uint32_t h2pack(float a, float b) {
    __half2 h = __floats2half2_rn(a, b);
    return *(uint32_t*)&h;
}
__device__ __forceinline__ void mma_f16(float& c0, float& c1, float& c2, float& c3,
                                        uint32_t a0, uint32_t a1, uint32_t a2, uint32_t a3,
                                        uint32_t b0, uint32_t b1) {
    asm volatile(
        "mma.sync.aligned.m16n8k16.row.col.f32.f16.f16.f32 "
        "{%0,%1,%2,%3}, {%4,%5,%6,%7}, {%8,%9}, {%0,%1,%2,%3};"
        : "+f"(c0), "+f"(c1), "+f"(c2), "+f"(c3)
        : "r"(a0), "r"(a1), "r"(a2), "r"(a3), "r"(b0), "r"(b1));
}
__device__ __forceinline__ void cp_async16(uint32_t smem_addr, const void* gsrc, uint32_t src_bytes) {
    asm volatile("cp.async.cg.shared.global [%0], [%1], 16, %2;\n"
                 :: "r"(smem_addr), "l"(gsrc), "r"(src_bytes));
}
__device__ __forceinline__ void cp_commit() {
    asm volatile("cp.async.commit_group;\n");
}
template <int N>
__device__ __forceinline__ void cp_wait() {
    asm volatile("cp.async.wait_group %0;\n" :: "n"(N));
}

// ===========================================================================
// Kernel 0: fp32 -> fp16 conversion
// ===========================================================================
#define NX4  (NTOK*64)
#define NWI4 (F3*64)
#define NWO4 (EMB*64)
__global__ __launch_bounds__(256) void cvt_kernel(
    const float* __restrict__ x,
    const float* __restrict__ wi,
    const float* __restrict__ wo)
{
    int i = blockIdx.x * blockDim.x + threadIdx.x;
    float4 v;
    uint2* dst;
    if (i < NX4)                 { v = ((const float4*)x)[i];  dst = (uint2*)g_xh + i; }
    else if (i < NX4 + NWI4)     { int j = i - NX4;  v = ((const float4*)wi)[j]; dst = (uint2*)g_wih + j; }
    else if (i < NX4 + NWI4 + NWO4) { int j = i - NX4 - NWI4; v = ((const float4*)wo)[j]; dst = (uint2*)g_woh + j; }
    else return;
    uint2 r;
    r.x = h2pack(v.x, v.y);
    r.y = h2pack(v.z, v.w);
    *dst = r;
}

// ===========================================================================
// Kernel 1: QKV (fp16 MMA, BM=128 BN=64 BK=32, 3-stage) — unchanged from R10
// ===========================================================================
__global__ __launch_bounds__(128) void qkv_h_kernel(const float* __restrict__ bias)
{
    __shared__ __align__(16) uint32_t As[3 * 128 * QP];
    __shared__ __align__(16) uint32_t Bs[3 * 64 * QP];

    const int n0 = blockIdx.x * 128;
    const int f0 = blockIdx.y * 64;
    const int tid = threadIdx.x;
    const int wid = tid >> 5;
    const int lane = tid & 31;
    const int g = lane >> 2;
    const int t = lane & 3;
    const int rw = 32 * wid;

    float C[8][2][4];
#pragma unroll
    for (int nn = 0; nn < 8; nn++)
#pragma unroll
        for (int b = 0; b < 2; b++)
#pragma unroll
            for (int e = 0; e < 4; e++) C[nn][b][e] = 0.f;

    const uint32_t as_base = (uint32_t)__cvta_generic_to_shared(As);
    const uint32_t bs_base = (uint32_t)__cvta_generic_to_shared(Bs);

    auto load_stage = [&](int kc, int st) {
        int k0 = kc * 16;
        uint32_t a_st = as_base + st * (128 * QP) * 4;
        uint32_t b_st = bs_base + st * (64 * QP) * 4;
#pragma unroll
        for (int i = 0; i < 4; i++) {
            int idx = tid + i * 128;
            int row = idx >> 2;
            int ch  = idx & 3;
            int gn = n0 + row;
            bool ok = (gn < NTOK);
            cp_async16(a_st + (row * QP + ch * 4) * 4,
                       g_xh + (size_t)(ok ? gn : 0) * 128 + k0 + ch * 4, ok ? 16u : 0u);
        }
#pragma unroll
        for (int i = 0; i < 2; i++) {
            int idx = tid + i * 128;
            int row = idx >> 2;
            int ch  = idx & 3;
            cp_async16(b_st + (row * QP + ch * 4) * 4,
                       g_wih + (size_t)(f0 + row) * 128 + k0 + ch * 4, 16u);
        }
        cp_commit();
    };

    load_stage(0, 0);
    load_stage(1, 1);

    for (int kc = 0; kc < 8; kc++) {
        __syncthreads();
        if (kc + 2 < 8) { load_stage(kc + 2, (kc + 2) % 3); cp_wait<2>(); }
        else if (kc + 1 < 8) { cp_wait<1>(); }
        else { cp_wait<0>(); }
        __syncthreads();

        const uint32_t* as = As + (kc % 3) * (128 * QP);
        const uint32_t* bs = Bs + (kc % 3) * (64 * QP);

#pragma unroll
        for (int s = 0; s < 2; s++) {
            int wl = 8 * s + t;
            int wh = wl + 4;
            uint32_t a00 = as[(rw + g)      * QP + wl];
            uint32_t a01 = as[(rw + g + 8)  * QP + wl];
            uint32_t a02 = as[(rw + g)      * QP + wh];
            uint32_t a03 = as[(rw + g + 8)  * QP + wh];
            uint32_t a10 = as[(rw + g + 16) * QP + wl];
            uint32_t a11 = as[(rw + g + 24) * QP + wl];
            uint32_t a12 = as[(rw + g + 16) * QP + wh];
            uint32_t a13 = as[(rw + g + 24) * QP + wh];
#pragma unroll
            for (int nn = 0; nn < 8; nn++) {
                int fr = 8 * nn + g;
                uint32_t b0 = bs[fr * QP + wl];
                uint32_t b1 = bs[fr * QP + wh];
                mma_f16(C[nn][0][0], C[nn][0][1], C[nn][0][2], C[nn][0][3],
                        a00, a01, a02, a03, b0, b1);
                mma_f16(C[nn][1][0], C[nn][1][1], C[nn][1][2], C[nn][1][3],
                        a10, a11, a12, a13, b0, b1);
            }
        }
    }

    const float QS = 0.17677669529663687f * 1.4426950408889634f;

#pragma unroll
    for (int blk = 0; blk < 2; blk++) {
#pragma unroll
        for (int half = 0; half < 2; half++) {
            int n = n0 + 32 * wid + 16 * blk + 8 * half + g;
            if (n >= NTOK) continue;
            int b = n / SEQ;
            int l = n % SEQ;
#pragma unroll
            for (int nn = 0; nn < 8; nn++) {
                int f = f0 + 8 * nn + 2 * t;
                float v0 = C[nn][blk][2 * half]     + bias[f];
                float v1 = C[nn][blk][2 * half + 1] + bias[f + 1];
                int which = f >> 8;
                int e = f & 255;
                int h = e >> 5;
                int d = e & 31;
                int bh = b * NHEAD + h;
                if (which == 0) {
                    g_qh[((size_t)bh * SEQ + l) * 16 + (d >> 1)] = h2pack(v0 * QS, v1 * QS);
                } else if (which == 1) {
                    g_kh[((size_t)bh * SEQ + l) * 16 + (d >> 1)] = h2pack(v0, v1);
                } else {
                    g_vt[((size_t)bh * HDIM + d)     * SEQP + l] = __float2half(v0);
                    g_vt[((size_t)bh * HDIM + d + 1) * SEQP + l] = __float2half(v1);
                }
            }
        }
    }
}

// ===========================================================================
// Kernel 2: flash attention fp16. half2 exp2; lsum via ones-column MMA;
// mask-free fast path for interior tiles; double-buffered KV staging.
// Vt smem has 40 d-rows: rows 32..39 are {ones, zeros...} constants.
// ===========================================================================
#define VTROWS 40
#define VTSTRIDE (VTROWS*32)

__global__ __launch_bounds__(256) void attn_f16_kernel()
{
    const int bh  = blockIdx.y;
    const int l0  = blockIdx.x * 128;
    const int tid = threadIdx.x;
    const int wid = tid >> 5;
    const int lane = tid & 31;
    const int g = lane >> 2;
    const int t = lane & 3;
    const int r_lo = l0 + wid * 16 + g;
    const int r_hi = r_lo + 8;

    __shared__ __align__(16) uint32_t Ks[2 * 64 * 20];
    __shared__ __align__(16) uint32_t Vts[2 * VTSTRIDE];

    const uint32_t ks_base = (uint32_t)__cvta_generic_to_shared(Ks);
    const uint32_t vt_base = (uint32_t)__cvta_generic_to_shared(Vts);

    // init ones/zeros rows 32..39 of both V buffers
    for (int i = tid; i < 2 * 8 * 32; i += 256) {
        int buf = i >> 8;
        int w = i & 255;
        int row = 32 + (w >> 5);
        int word = w & 31;
        Vts[buf * VTSTRIDE + row * 32 + word] = (row == 32) ? 0x3C003C00u : 0u;
    }

    const uint32_t* qw = g_qh + (size_t)bh * SEQ * 16;
    uint32_t Aq[2][4];
#pragma unroll
    for (int s = 0; s < 2; s++) {
        Aq[s][0] = Aq[s][1] = Aq[s][2] = Aq[s][3] = 0;
        if (r_lo < SEQ) {
            Aq[s][0] = qw[(size_t)r_lo * 16 + t + 8 * s];
            Aq[s][2] = qw[(size_t)r_lo * 16 + t + 4 + 8 * s];
        }
        if (r_hi < SEQ) {
            Aq[s][1] = qw[(size_t)r_hi * 16 + t + 8 * s];
            Aq[s][3] = qw[(size_t)r_hi * 16 + t + 4 + 8 * s];
        }
    }

    float o[5][4];
#pragma unroll
    for (int nn = 0; nn < 5; nn++)
#pragma unroll
        for (int e = 0; e < 4; e++) o[nn][e] = 0.f;

    float m_lo = -INFINITY, m_hi = -INFINITY;

    const int glo = (r_lo < PADSZ) ? (r_lo / GROUPSZ) : -1;
    const int ghi = (r_hi < PADSZ) ? (r_hi / GROUPSZ) : -1;
    const bool blk_has_pad = (l0 < PADSZ);
    const int gminb = l0 / GROUPSZ;
    const int gmaxb = (min(l0 + 127, PADSZ - 1)) / GROUPSZ;

    auto tile_needed = [&](int m0) -> bool {
        if (m0 + 64 > PADSZ) return true;
        if (!blk_has_pad) return false;
        int gt0 = m0 / GROUPSZ, gt1 = (m0 + 63) / GROUPSZ;
        return !(gmaxb < gt0 || gminb > gt1);
    };

    const int k_row = tid >> 2;
    const int k_ch  = tid & 3;
    const int v_d   = tid >> 3;
    const int v_ch  = tid & 7;
    const uint32_t* kbh = g_kh + (size_t)bh * SEQ * 16;
    const __half*   vbh = g_vt + (size_t)bh * HDIM * SEQP;

    auto load_tile = [&](int m0, int buf) {
        uint32_t k_dst = ks_base + (buf * (64 * 20) + k_row * 20 + k_ch * 4) * 4;
        uint32_t v_dst = vt_base + (buf * VTSTRIDE + v_d * 32 + ((v_ch * 4) ^ ((v_d & 7) << 2))) * 4;
        int m = m0 + k_row;
        cp_async16(k_dst, kbh + (size_t)(m < SEQ ? m : 0) * 16 + k_ch * 4,
                   (m < SEQ) ? 16u : 0u);
        int ms = m0 + v_ch * 8;
        uint32_t nb = 0;
        if (ms < SEQ) { int rem = (SEQ - ms) * 2; nb = rem >= 16 ? 16u : (uint32_t)rem; }
        cp_async16(v_dst, vbh + (size_t)v_d * SEQP + ms, nb);
        cp_commit();
    };

    int m0 = 0;
    while (m0 < SEQ && !tile_needed(m0)) m0 += 64;
    if (m0 < SEQ) load_tile(m0, 0);
    int buf = 0;

    while (m0 < SEQ) {
        int mn = m0 + 64;
        while (mn < SEQ && !tile_needed(mn)) mn += 64;

        __syncthreads();
        if (mn < SEQ) { load_tile(mn, buf ^ 1); cp_wait<1>(); }
        else          { cp_wait<0>(); }
        __syncthreads();

        const uint32_t* ks = Ks + buf * (64 * 20);
        const uint32_t* vs = Vts + buf * VTSTRIDE;

        // --- scores S = Q @ K^T ---
        float S[8][4];
#pragma unroll
        for (int j = 0; j < 8; j++) {
            S[j][0] = 0.f; S[j][1] = 0.f; S[j][2] = 0.f; S[j][3] = 0.f;
            int kb = (8 * j + g) * 20;
#pragma unroll
            for (int s = 0; s < 2; s++) {
                uint32_t b0 = ks[kb + t + 8 * s];
                uint32_t b1 = ks[kb + t + 4 + 8 * s];
                mma_f16(S[j][0], S[j][1], S[j][2], S[j][3],
                        Aq[s][0], Aq[s][1], Aq[s][2], Aq[s][3], b0, b1);
            }
        }

        // --- mask (only when needed) + rowmax ---
        const bool domask = (m0 < PADSZ) || (m0 + 64 > SEQ);
        float tmax_lo = -INFINITY, tmax_hi = -INFINITY;
        if (domask) {
#pragma unroll
            for (int j = 0; j < 8; j++) {
                int c0 = m0 + 8 * j + 2 * t;
                int c1 = c0 + 1;
                int mg0 = c0 / GROUPSZ;
                int mg1 = c1 / GROUPSZ;
                bool b0lo = (c0 >= SEQ) || (c0 < PADSZ && mg0 != glo);
                bool b1lo = (c1 >= SEQ) || (c1 < PADSZ && mg1 != glo);
                bool b0hi = (c0 >= SEQ) || (c0 < PADSZ && mg0 != ghi);
                bool b1hi = (c1 >= SEQ) || (c1 < PADSZ && mg1 != ghi);
                if (b0lo) S[j][0] = -INFINITY;
                if (b1lo) S[j][1] = -INFINITY;
                if (b0hi) S[j][2] = -INFINITY;
                if (b1hi) S[j][3] = -INFINITY;
                tmax_lo = fmaxf(tmax_lo, fmaxf(S[j][0], S[j][1]));
                tmax_hi = fmaxf(tmax_hi, fmaxf(S[j][2], S[j][3]));
            }
        } else {
#pragma unroll
            for (int j = 0; j < 8; j++) {
                tmax_lo = fmaxf(tmax_lo, fmaxf(S[j][0], S[j][1]));
                tmax_hi = fmaxf(tmax_hi, fmaxf(S[j][2], S[j][3]));
            }
        }
        tmax_lo = fmaxf(tmax_lo, __shfl_xor_sync(0xffffffffu, tmax_lo, 1));
        tmax_lo = fmaxf(tmax_lo, __shfl_xor_sync(0xffffffffu, tmax_lo, 2));
        tmax_hi = fmaxf(tmax_hi, __shfl_xor_sync(0xffffffffu, tmax_hi, 1));
        tmax_hi = fmaxf(tmax_hi, __shfl_xor_sync(0xffffffffu, tmax_hi, 2));

        float mnew_lo = fmaxf(m_lo, tmax_lo);
        float mnew_hi = fmaxf(m_hi, tmax_hi);
        float msafe_lo = (mnew_lo == -INFINITY) ? 0.f : mnew_lo;
        float msafe_hi = (mnew_hi == -INFINITY) ? 0.f : mnew_hi;
        float corr_lo = fast_exp2(m_lo - msafe_lo);
        float corr_hi = fast_exp2(m_hi - msafe_hi);
        m_lo = mnew_lo; m_hi = mnew_hi;

#pragma unroll
        for (int nn = 0; nn < 5; nn++) {
            o[nn][0] *= corr_lo; o[nn][1] *= corr_lo;
            o[nn][2] *= corr_hi; o[nn][3] *= corr_hi;
        }

        // --- P = exp2(S - m) in half2 (directly the PV A-fragments) ---
        uint32_t P01[8], P23[8];
#pragma unroll
        for (int j = 0; j < 8; j++) {
            uint32_t s01, s23;
            asm("cvt.rn.f16x2.f32 %0, %1, %2;" : "=r"(s01)
                : "f"(S[j][1] - msafe_lo), "f"(S[j][0] - msafe_lo));
            asm("cvt.rn.f16x2.f32 %0, %1, %2;" : "=r"(s23)
                : "f"(S[j][3] - msafe_hi), "f"(S[j][2] - msafe_hi));
            asm("ex2.approx.f16x2 %0, %1;" : "=r"(P01[j]) : "r"(s01));
            asm("ex2.approx.f16x2 %0, %1;" : "=r"(P23[j]) : "r"(s23));
        }

        // --- PV (+ ones-column accumulates lsum into o[4]) ---
#pragma unroll
        for (int c = 0; c < 4; c++) {
            uint32_t pa0 = P01[2 * c];
            uint32_t pa1 = P23[2 * c];
            uint32_t pa2 = P01[2 * c + 1];
            uint32_t pa3 = P23[2 * c + 1];
#pragma unroll
            for (int nn = 0; nn < 5; nn++) {
                int vr = (8 * nn + g) * 32;
                uint32_t b0 = vs[vr + ((8 * c + t)     ^ (g << 2))];
                uint32_t b1 = vs[vr + ((8 * c + t + 4) ^ (g << 2))];
                mma_f16(o[nn][0], o[nn][1], o[nn][2], o[nn][3],
                        pa0, pa1, pa2, pa3, b0, b1);
            }
        }

        buf ^= 1;
        m0 = mn;
    }

    // lsum lives in o[4][0]/o[4][2] of the t==0 lane of each quad
    float l_lo = __shfl_sync(0xffffffffu, o[4][0], lane & ~3);
    float l_hi = __shfl_sync(0xffffffffu, o[4][2], lane & ~3);
    float inv_lo = 1.0f / l_lo;
    float inv_hi = 1.0f / l_hi;

    const int b = bh >> 3;
    const int h = bh & 7;
    if (r_lo < SEQ) {
        uint32_t* dst = &g_ctxh[((size_t)b * SEQ + r_lo) * 128 + h * 16];
#pragma unroll
        for (int nn = 0; nn < 4; nn++)
            dst[4 * nn + t] = h2pack(o[nn][0] * inv_lo, o[nn][1] * inv_lo);
    }
    if (r_hi < SEQ) {
        uint32_t* dst = &g_ctxh[((size_t)b * SEQ + r_hi) * 128 + h * 16];
#pragma unroll
        for (int nn = 0; nn < 4; nn++)
            dst[4 * nn + t] = h2pack(o[nn][2] * inv_hi, o[nn][3] * inv_hi);
    }
}

// ===========================================================================
// Kernel 3: fused out = LN(x + ctx @ out_w^T + out_b)
// BM=64, BN=256, BK=32 fp16, 256 threads (2 bands x 4 quads), pitch-16 XOR swz
// ===========================================================================
__device__ __forceinline__ int swz16(int r) { return ((r >> 1) & 3) << 2; }

__global__ __launch_bounds__(256) void out_ln_kernel(
    const float* __restrict__ x,
    const float* __restrict__ bias,
    const float* __restrict__ gamma,
    const float* __restrict__ beta,
    float* __restrict__ out)
{
    __shared__ __align__(16) uint32_t As[2 * 64 * 16];
    __shared__ __align__(16) uint32_t Bs[2 * 256 * 16];
    __shared__ float s_sum[64][4];
    __shared__ float s_sqs[64][4];

    const int n0 = blockIdx.x * 64;
    const int tid = threadIdx.x;
    const int wid = tid >> 5;
    const int lane = tid & 31;
    const int g = lane >> 2;
    const int t = lane & 3;
    const int band = wid >> 2;     // 0..1 (32 rows each)
    const int quad = wid & 3;      // 0..3 (64 cols each)

    float C[8][2][4];
#pragma unroll
    for (int nn = 0; nn < 8; nn++)
#pragma unroll
        for (int b = 0; b < 2; b++)
#pragma unroll
            for (int e = 0; e < 4; e++) C[nn][b][e] = 0.f;

    const uint32_t as_base = (uint32_t)__cvta_generic_to_shared(As);
    const uint32_t bs_base = (uint32_t)__cvta_generic_to_shared(Bs);

    auto load_stage = [&](int kc, int st) {
        int k0 = kc * 16;
        uint32_t a_st = as_base + st * (64 * 16) * 4;
        uint32_t b_st = bs_base + st * (256 * 16) * 4;
        // A: 64 rows x 4 chunks = 256 tasks (1/thread)
        {
            int row = tid >> 2;
            int ch  = tid & 3;
            int gn = n0 + row;
            bool ok = (gn < NTOK);
            cp_async16(a_st + (row * 16 + ((ch * 4) ^ swz16(row))) * 4,
                       g_ctxh + (size_t)(ok ? gn : 0) * 128 + k0 + ch * 4, ok ? 16u : 0u);
        }
        // B: 256 rows x 4 chunks = 1024 tasks (4/thread)
#pragma unroll
        for (int i = 0; i < 4; i++) {
            int idx = tid + i * 256;
            int row = idx >> 2;
            int ch  = idx & 3;
            cp_async16(b_st + (row * 16 + ((ch * 4) ^ swz16(row))) * 4,
                       g_woh + (size_t)row * 128 + k0 + ch * 4, 16u);
        }
        cp_commit();
    };

    load_stage(0, 0);

    const int Rb = 32 * band;
    const int sA = swz16(g);   // rows Rb+g, +8, +16, +24 share swz16 (depends on (r>>1)&3; +8 keeps it)

    for (int kc = 0; kc < 8; kc++) {
        __syncthreads();
        if (kc + 1 < 8) { load_stage(kc + 1, (kc + 1) & 1); cp_wait<1>(); }
        else            { cp_wait<0>(); }
        __syncthreads();

        const uint32_t* as = As + (kc & 1) * (64 * 16);
        const uint32_t* bs = Bs + (kc & 1) * (256 * 16);

#pragma unroll
        for (int s = 0; s < 2; s++) {
            int wl = (8 * s + t) ^ sA;
            int wh = (8 * s + t + 4) ^ sA;
            uint32_t a00 = as[(Rb + g)      * 16 + wl];
            uint32_t a01 = as[(Rb + g + 8)  * 16 + wl];
            uint32_t a02 = as[(Rb + g)      * 16 + wh];
            uint32_t a03 = as[(Rb + g + 8)  * 16 + wh];
            uint32_t a10 = as[(Rb + g + 16) * 16 + wl];
            uint32_t a11 = as[(Rb + g + 24) * 16 + wl];
            uint32_t a12 = as[(Rb + g + 16) * 16 + wh];
            uint32_t a13 = as[(Rb + g + 24) * 16 + wh];
#pragma unroll
            for (int nn = 0; nn < 8; nn++) {
                int fr = 64 * quad + 8 * nn + g;
                int wbl = (8 * s + t) ^ swz16(fr);
                int wbh = (8 * s + t + 4) ^ swz16(fr);
                uint32_t b0 = bs[fr * 16 + wbl];
                uint32_t b1 = bs[fr * 16 + wbh];
                mma_f16(C[nn][0][0], C[nn][0][1], C[nn][0][2], C[nn][0][3],
                        a00, a01, a02, a03, b0, b1);
                mma_f16(C[nn][1][0], C[nn][1][1], C[nn][1][2], C[nn][1][3],
                        a10, a11, a12, a13, b0, b1);
            }
        }
    }

    // epilogue: bias + residual, LN stats over 4 rows/thread-quad
    const int r0 = n0 + Rb + g;          // rows r0, r0+8, r0+16, r0+24
    float sum[4] = {0.f, 0.f, 0.f, 0.f};
    float sqs[4] = {0.f, 0.f, 0.f, 0.f};
#pragma unroll
    for (int nn = 0; nn < 8; nn++) {
        int f = 64 * quad + 8 * nn + 2 * t;
        float b0 = bias[f], b1 = bias[f + 1];
#pragma unroll
        for (int blk = 0; blk < 2; blk++) {
#pragma unroll
            for (int half = 0; half < 2; half++) {
                int r = r0 + 16 * blk + 8 * half;
                int e0 = 2 * half, e1 = e0 + 1;
                if (r < NTOK) {
                    float2 xr = *(const float2*)&x[(size_t)r * 256 + f];
                    C[nn][blk][e0] += b0 + xr.x;
                    C[nn][blk][e1] += b1 + xr.y;
                }
                int ridx = 2 * blk + half;
                sum[ridx] += C[nn][blk][e0] + C[nn][blk][e1];
                sqs[ridx] += C[nn][blk][e0] * C[nn][blk][e0] + C[nn][blk][e1] * C[nn][blk][e1];
            }
        }
    }
#pragma unroll
    for (int ridx = 0; ridx < 4; ridx++) {
        sum[ridx] += __shfl_xor_sync(0xffffffffu, sum[ridx], 1);
        sum[ridx] += __shfl_xor_sync(0xffffffffu, sum[ridx], 2);
        sqs[ridx] += __shfl_xor_sync(0xffffffffu, sqs[ridx], 1);
        sqs[ridx] += __shfl_xor_sync(0xffffffffu, sqs[ridx], 2);
    }
    if (t == 0) {
#pragma unroll
        for (int ridx = 0; ridx < 4; ridx++) {
            s_sum[Rb + g + 8 * ridx][quad] = sum[ridx];
            s_sqs[Rb + g + 8 * ridx][quad] = sqs[ridx];
        }
    }
    __syncthreads();

    float mean[4], rs[4];
#pragma unroll
    for (int ridx = 0; ridx < 4; ridx++) {
        int sr = Rb + g + 8 * ridx;
        float S1 = s_sum[sr][0] + s_sum[sr][1] + s_sum[sr][2] + s_sum[sr][3];
        float S2 = s_sqs[sr][0] + s_sqs[sr][1] + s_sqs[sr][2] + s_sqs[sr][3];
        mean[ridx] = S1 * (1.0f / 256.0f);
        float var = S2 * (1.0f / 256.0f) - mean[ridx] * mean[ridx];
        rs[ridx] = rsqrtf(var + LNEPS);
    }

#pragma unroll
    for (int nn = 0; nn < 8; nn++) {
        int f = 64 * quad + 8 * nn + 2 * t;
        float gm0 = gamma[f], gm1 = gamma[f + 1];
        float bt0 = beta[f],  bt1 = beta[f + 1];
#pragma unroll
        for (int blk = 0; blk < 2; blk++) {
#pragma unroll
            for (int half = 0; half < 2; half++) {
                int r = r0 + 16 * blk + 8 * half;
                if (r >= NTOK) continue;
                int ridx = 2 * blk + half;
                int e0 = 2 * half;
                float2 w;
                w.x = (C[nn][blk][e0]     - mean[ridx]) * rs[ridx] * gm0 + bt0;
                w.y = (C[nn][blk][e0 + 1] - mean[ridx]) * rs[ridx] * gm1 + bt1;
                *(float2*)&out[(size_t)r * 256 + f] = w;
            }
        }
    }
}

// ---------------------------------------------------------------------------
extern "C" void kernel_launch(void* const* d_in, const int* in_sizes, int n_in,
                              void* d_out, int out_size)
{
    const float* x     = (const float*)d_in[0];
    const float* in_w  = (const float*)d_in[1];
    const float* in_b  = (const float*)d_in[2];
    const float* out_w = (const float*)d_in[3];
    const float* out_b = (const float*)d_in[4];
    const float* ln_g  = (const float*)d_in[5];
    const float* ln_b  = (const float*)d_in[6];
    float* out = (float*)d_out;

    cvt_kernel<<<(NX4 + NWI4 + NWO4 + 255) / 256, 256>>>(x, in_w, out_w);
    qkv_h_kernel<<<dim3((NTOK + 127) / 128, F3 / 64), 128>>>(in_b);
    attn_f16_kernel<<<dim3((SEQ + 127) / 128, BATCH * NHEAD), 256>>>();
    out_ln_kernel<<<(NTOK + 63) / 64, 256>>>(x, out_b, ln_g, ln_b, out);
}